// round 2
// baseline (speedup 1.0000x reference)
#include <cuda_runtime.h>
#include <cuda_bf16.h>
#include <mma.h>
#include <math.h>

namespace wm = nvcuda::wmma;
using bf16 = __nv_bfloat16;

// ---------------------------------------------------------------------------
// Problem constants
// ---------------------------------------------------------------------------
constexpr int B_      = 8;
constexpr int NSEQ    = 4096;
constexpr int MTOK    = B_ * NSEQ;          // 32768
constexpr int D       = 512;
constexpr int DFF     = 2048;
constexpr int HD      = 64;                 // head dim

// ---------------------------------------------------------------------------
// Scratch (static device globals -- allocation-free contract)
// ---------------------------------------------------------------------------
__device__ __align__(16) float g_seasonal[MTOK * D];
__device__ __align__(16) float g_trend   [MTOK * D];
__device__ __align__(16) bf16  g_lnhi    [MTOK * D];
__device__ __align__(16) bf16  g_lnlo    [MTOK * D];
__device__ __align__(16) bf16  g_qhi     [MTOK * D];
__device__ __align__(16) bf16  g_qlo     [MTOK * D];
__device__ __align__(16) bf16  g_khi     [MTOK * D];
__device__ __align__(16) bf16  g_klo     [MTOK * D];
__device__ __align__(16) bf16  g_vhi     [MTOK * D];
__device__ __align__(16) bf16  g_vlo     [MTOK * D];
__device__ __align__(16) bf16  g_lnb     [MTOK * D];
__device__ __align__(16) bf16  g_h       [MTOK * DFF];
__device__ __align__(16) float g_kvp     [4 * 64 * HD * HD];
__device__ __align__(16) bf16  g_Mhi     [B_ * D * D];
__device__ __align__(16) bf16  g_Mlo     [B_ * D * D];
__device__ __align__(16) bf16  g_Wqkv_hi [D * 3 * D];
__device__ __align__(16) bf16  g_Wqkv_lo [D * 3 * D];
__device__ __align__(16) bf16  g_Wf1b    [D * DFF];
__device__ __align__(16) bf16  g_Wf2b    [DFF * D];
__device__ __align__(16) float g_bqkv    [3 * D];

__device__ __forceinline__ void split2(float x, bf16& hi, bf16& lo) {
    hi = __float2bfloat16(x);
    lo = __float2bfloat16(x - __bfloat162float(hi));
}

__device__ __forceinline__ void cp16(void* dst, const void* src) {
    unsigned sd = (unsigned)__cvta_generic_to_shared(dst);
    asm volatile("cp.async.cg.shared.global [%0], [%1], 16;\n" :: "r"(sd), "l"(src));
}
__device__ __forceinline__ void cp_commit() {
    asm volatile("cp.async.commit_group;\n");
}

// ---------------------------------------------------------------------------
// 1. Weight conversion / splitting (tiny)
// ---------------------------------------------------------------------------
__global__ void convert_weights(const float* __restrict__ Wq, const float* __restrict__ Wk,
                                const float* __restrict__ Wv,
                                const float* __restrict__ bq, const float* __restrict__ bk,
                                const float* __restrict__ bv,
                                const float* __restrict__ Wf1, const float* __restrict__ Wf2) {
    int i = blockIdx.x * 256 + threadIdx.x;
    if (i < D * D) {
        int r = i >> 9, c = i & 511;
        size_t o = (size_t)r * (3 * D) + c;
        bf16 hi, lo;
        split2(Wq[i], hi, lo); g_Wqkv_hi[o]        = hi; g_Wqkv_lo[o]        = lo;
        split2(Wk[i], hi, lo); g_Wqkv_hi[o + 512]  = hi; g_Wqkv_lo[o + 512]  = lo;
        split2(Wv[i], hi, lo); g_Wqkv_hi[o + 1024] = hi; g_Wqkv_lo[o + 1024] = lo;
    }
    if (i < D * DFF) {
        g_Wf1b[i] = __float2bfloat16(Wf1[i]);
        g_Wf2b[i] = __float2bfloat16(Wf2[i]);
    }
    if (i < D) {
        g_bqkv[i]        = bq[i];
        g_bqkv[i + 512]  = bk[i];
        g_bqkv[i + 1024] = bv[i];
    }
}

// ---------------------------------------------------------------------------
// 2. Series decomposition + LayerNorm1 -> bf16 hi/lo
// ---------------------------------------------------------------------------
__global__ void __launch_bounds__(256) decomp_ln1(const float* __restrict__ x,
                                                  const float* __restrict__ g1,
                                                  const float* __restrict__ b1) {
    int m = blockIdx.x;
    int n = m & (NSEQ - 1);
    const float* xr = x + (size_t)m * D;
    __shared__ float sse[D];
    __shared__ float red[16];
    __shared__ float s_mean, s_inv;
    int t = threadIdx.x;
    float sum = 0.f, sq = 0.f;
#pragma unroll
    for (int i = 0; i < 2; i++) {
        int c = t + i * 256;
        float x0 = xr[c];
        float xm = (n > 0)        ? xr[c - D] : 0.f;
        float xp = (n < NSEQ - 1) ? xr[c + D] : 0.f;
        float tr = (xm + x0 + xp) * (1.f / 3.f);
        float se = x0 - tr;
        g_trend[(size_t)m * D + c]    = tr;
        g_seasonal[(size_t)m * D + c] = se;
        sse[c] = se;
        sum += se; sq += se * se;
    }
#pragma unroll
    for (int o = 16; o > 0; o >>= 1) {
        sum += __shfl_xor_sync(0xffffffffu, sum, o);
        sq  += __shfl_xor_sync(0xffffffffu, sq,  o);
    }
    if ((t & 31) == 0) { red[t >> 5] = sum; red[8 + (t >> 5)] = sq; }
    __syncthreads();
    if (t == 0) {
        float S = 0.f, Q = 0.f;
#pragma unroll
        for (int w = 0; w < 8; w++) { S += red[w]; Q += red[8 + w]; }
        float mean = S * (1.f / (float)D);
        float var  = Q * (1.f / (float)D) - mean * mean;
        s_mean = mean;
        s_inv  = rsqrtf(var + 1e-5f);
    }
    __syncthreads();
#pragma unroll
    for (int i = 0; i < 2; i++) {
        int c = t + i * 256;
        float v = (sse[c] - s_mean) * s_inv * g1[c] + b1[c];
        bf16 hi, lo; split2(v, hi, lo);
        size_t o = (size_t)m * D + c;
        g_lnhi[o] = hi;
        g_lnlo[o] = lo;
    }
}

// ---------------------------------------------------------------------------
// LayerNorm2 (seasonal -> bf16 single)
// ---------------------------------------------------------------------------
__global__ void __launch_bounds__(256) ln2_kernel(const float* __restrict__ g2,
                                                  const float* __restrict__ b2) {
    int m = blockIdx.x;
    const float* sr = g_seasonal + (size_t)m * D;
    __shared__ float sse[D];
    __shared__ float red[16];
    __shared__ float s_mean, s_inv;
    int t = threadIdx.x;
    float sum = 0.f, sq = 0.f;
#pragma unroll
    for (int i = 0; i < 2; i++) {
        int c = t + i * 256;
        float se = sr[c];
        sse[c] = se;
        sum += se; sq += se * se;
    }
#pragma unroll
    for (int o = 16; o > 0; o >>= 1) {
        sum += __shfl_xor_sync(0xffffffffu, sum, o);
        sq  += __shfl_xor_sync(0xffffffffu, sq,  o);
    }
    if ((t & 31) == 0) { red[t >> 5] = sum; red[8 + (t >> 5)] = sq; }
    __syncthreads();
    if (t == 0) {
        float S = 0.f, Q = 0.f;
#pragma unroll
        for (int w = 0; w < 8; w++) { S += red[w]; Q += red[8 + w]; }
        float mean = S * (1.f / (float)D);
        float var  = Q * (1.f / (float)D) - mean * mean;
        s_mean = mean;
        s_inv  = rsqrtf(var + 1e-5f);
    }
    __syncthreads();
#pragma unroll
    for (int i = 0; i < 2; i++) {
        int c = t + i * 256;
        float v = (sse[c] - s_mean) * s_inv * g2[c] + b2[c];
        g_lnb[(size_t)m * D + c] = __float2bfloat16(v);
    }
}

// ---------------------------------------------------------------------------
// kv partials via split-bf16 tensor cores.
// Per (chunk, b, h): kv[d,f] += sum_{n in chunk} k[n,d] * v[n,f]
// A = k viewed col-major (d x n), B = v row-major (n x f).  3-pass split.
// ---------------------------------------------------------------------------
__global__ void __launch_bounds__(256) kv_mma() {
    int bh    = blockIdx.x & 63;
    int chunk = blockIdx.x >> 6;
    int b = bh >> 3, h = bh & 7;
    size_t base = (size_t)b * NSEQ * D + h * HD;

    __shared__ __align__(16) bf16 sk [2][32][72];
    __shared__ __align__(16) bf16 skl[2][32][72];
    __shared__ __align__(16) bf16 sv [2][32][72];
    __shared__ __align__(16) bf16 svl[2][32][72];

    int t = threadIdx.x;
    int warp = t >> 5;
    int wd = (warp >> 1) * 16;   // d rows
    int wf = (warp & 1) * 32;    // f cols

    wm::fragment<wm::accumulator, 16, 16, 16, float> acc[2];
#pragma unroll
    for (int j = 0; j < 2; j++) wm::fill_fragment(acc[j], 0.f);

    int n0base = chunk * (NSEQ / 4);
    int r = t >> 3, c = (t & 7) * 8;

    // preload stage 0
    {
        size_t g = base + (size_t)(n0base + r) * D + c;
        cp16(&sk [0][r][c], g_khi + g);
        cp16(&skl[0][r][c], g_klo + g);
        cp16(&sv [0][r][c], g_vhi + g);
        cp16(&svl[0][r][c], g_vlo + g);
        cp_commit();
    }
    constexpr int NIT = (NSEQ / 4) / 32;   // 32
    for (int it = 0; it < NIT; it++) {
        if (it + 1 < NIT) {
            int st = (it + 1) & 1;
            size_t g = base + (size_t)(n0base + (it + 1) * 32 + r) * D + c;
            cp16(&sk [st][r][c], g_khi + g);
            cp16(&skl[st][r][c], g_klo + g);
            cp16(&sv [st][r][c], g_vhi + g);
            cp16(&svl[st][r][c], g_vlo + g);
            cp_commit();
            asm volatile("cp.async.wait_group 1;\n");
        } else {
            asm volatile("cp.async.wait_group 0;\n");
        }
        __syncthreads();
        int st = it & 1;
#pragma unroll
        for (int kk = 0; kk < 32; kk += 16) {
            wm::fragment<wm::matrix_a, 16, 16, 16, bf16, wm::col_major> ah, al;
            wm::fragment<wm::matrix_b, 16, 16, 16, bf16, wm::row_major> bh[2], bl[2];
            wm::load_matrix_sync(ah, &sk [st][kk][wd], 72);
            wm::load_matrix_sync(al, &skl[st][kk][wd], 72);
#pragma unroll
            for (int j = 0; j < 2; j++) {
                wm::load_matrix_sync(bh[j], &sv [st][kk][wf + j * 16], 72);
                wm::load_matrix_sync(bl[j], &svl[st][kk][wf + j * 16], 72);
            }
#pragma unroll
            for (int j = 0; j < 2; j++) {
                wm::mma_sync(acc[j], ah, bh[j], acc[j]);
                wm::mma_sync(acc[j], ah, bl[j], acc[j]);
                wm::mma_sync(acc[j], al, bh[j], acc[j]);
            }
        }
        __syncthreads();
    }
    float* dst = g_kvp + (size_t)chunk * (64 * HD * HD) + (size_t)bh * (HD * HD);
#pragma unroll
    for (int j = 0; j < 2; j++)
        wm::store_matrix_sync(dst + wd * HD + wf + j * 16, acc[j], HD, wm::mem_row_major);
}

// ---------------------------------------------------------------------------
// M[b, h*64+d, j] = sum_f kv[b,h,d,f] * Wo[h*64+f, j]   (fp32, split out)
// ---------------------------------------------------------------------------
__global__ void __launch_bounds__(256) kvwo_kernel(const float* __restrict__ Wo) {
    int bh = blockIdx.x >> 2, jt = blockIdx.x & 3;
    int b = bh >> 3, h = bh & 7;
    __shared__ __align__(16) float skv[HD][HD];
    int t = threadIdx.x;
#pragma unroll
    for (int i = 0; i < 16; i++) {
        int idx = t + i * 256;
        float s = 0.f;
#pragma unroll
        for (int c = 0; c < 4; c++)
            s += g_kvp[(size_t)c * (64 * HD * HD) + (size_t)bh * (HD * HD) + idx];
        reinterpret_cast<float*>(skv)[idx] = s;
    }
    __syncthreads();
    int j0 = jt * 128;
    int d0 = (t >> 5) * 8;
    int jj = (t & 31) * 4;
    float acc[8][4] = {};
    for (int f = 0; f < HD; f++) {
        float4 w4 = *reinterpret_cast<const float4*>(&Wo[(size_t)(h * HD + f) * D + j0 + jj]);
        float w[4] = {w4.x, w4.y, w4.z, w4.w};
#pragma unroll
        for (int i = 0; i < 8; i++) {
            float kv = skv[d0 + i][f];
#pragma unroll
            for (int j = 0; j < 4; j++) acc[i][j] += kv * w[j];
        }
    }
#pragma unroll
    for (int i = 0; i < 8; i++)
#pragma unroll
        for (int j = 0; j < 4; j++) {
            size_t o = (size_t)b * (D * D) + (size_t)(h * HD + d0 + i) * D + j0 + jj + j;
            bf16 hi, lo;
            split2(acc[i][j], hi, lo);
            g_Mhi[o] = hi;
            g_Mlo[o] = lo;
        }
}

// ---------------------------------------------------------------------------
// Pipelined wmma GEMM: 128x128x32 tile, 2-stage cp.async double buffering.
// Split sites run 3 bf16 passes (hi*hi + hi*lo + lo*hi) for ~fp32 accuracy.
// ---------------------------------------------------------------------------
constexpr int BM = 128, BN = 128, BK = 32;
#define S_QKV  0
#define S_ATTN 1
#define S_FFN1 2
#define S_FFN2 3

template <int SITE> struct GemmSmem {
    static constexpr bool SPLIT = (SITE == S_QKV || SITE == S_ATTN);
    static constexpr int AP = 40, BP = 136;
    static constexpr int A_ELEMS = 2 * BM * AP;      // per split-half (2 stages)
    static constexpr int B_ELEMS = 2 * BK * BP;
    static constexpr int TOTAL_ELEMS = (SPLIT ? 2 : 1) * (A_ELEMS + B_ELEMS);
    static constexpr int BYTES = TOTAL_ELEMS * 2;
};

template <int SITE>
__global__ void __launch_bounds__(256) gemm_pipe(const float* __restrict__ bias,
                                                 float* __restrict__ outp) {
    constexpr bool SPLIT = (SITE == S_QKV || SITE == S_ATTN);
    constexpr int K   = (SITE == S_FFN2) ? 2048 : 512;
    constexpr int LDA = (SITE == S_FFN2) ? 2048 : 512;
    constexpr int LDB = (SITE == S_QKV) ? 1536 : ((SITE == S_FFN1) ? 2048 : 512);
    constexpr int NIT = K / BK;
    constexpr int AP = GemmSmem<SITE>::AP, BP = GemmSmem<SITE>::BP;
    constexpr int A_ELEMS = GemmSmem<SITE>::A_ELEMS;
    constexpr int B_ELEMS = GemmSmem<SITE>::B_ELEMS;

    extern __shared__ __align__(16) char dynsmem[];
    bf16* sAh = (bf16*)dynsmem;
    bf16* sAl = sAh + A_ELEMS;                         // SPLIT only
    bf16* sBh = sAh + (SPLIT ? 2 : 1) * A_ELEMS;
    bf16* sBl = sBh + B_ELEMS;                         // SPLIT only

    const bf16 *Ah = nullptr, *Alo = nullptr, *Bhp = nullptr, *Blo = nullptr;
    if constexpr (SITE == S_QKV)  { Ah = g_lnhi; Alo = g_lnlo; Bhp = g_Wqkv_hi; Blo = g_Wqkv_lo; }
    if constexpr (SITE == S_ATTN) { Ah = g_qhi;  Alo = g_qlo;
                                    Bhp = g_Mhi + (size_t)blockIdx.z * (D * D);
                                    Blo = g_Mlo + (size_t)blockIdx.z * (D * D); }
    if constexpr (SITE == S_FFN1) { Ah = g_lnb;  Bhp = g_Wf1b; }
    if constexpr (SITE == S_FFN2) { Ah = g_h;    Bhp = g_Wf2b; }

    int bm = blockIdx.y * BM + ((SITE == S_ATTN) ? blockIdx.z * NSEQ : 0);
    int bn = blockIdx.x * BN;
    int warp = threadIdx.x >> 5, lane = threadIdx.x & 31;
    int wmr = (warp >> 2) * 64;
    int wnc = (warp & 3) * 32;

    wm::fragment<wm::accumulator, 16, 16, 16, float> acc[4][2];
#pragma unroll
    for (int i = 0; i < 4; i++)
#pragma unroll
        for (int j = 0; j < 2; j++) wm::fill_fragment(acc[i][j], 0.f);

    auto stageLoad = [&](int st, int k0) {
#pragma unroll
        for (int i = 0; i < 2; i++) {
            int ch = threadIdx.x + i * 256;
            int r = ch >> 2, c = (ch & 3) * 8;
            size_t g = (size_t)(bm + r) * LDA + k0 + c;
            cp16(sAh + st * BM * AP + r * AP + c, Ah + g);
            if constexpr (SPLIT)
                cp16(sAl + st * BM * AP + r * AP + c, Alo + g);
        }
#pragma unroll
        for (int i = 0; i < 2; i++) {
            int ch = threadIdx.x + i * 256;
            int r = ch >> 4, c = (ch & 15) * 8;
            size_t g = (size_t)(k0 + r) * LDB + bn + c;
            cp16(sBh + st * BK * BP + r * BP + c, Bhp + g);
            if constexpr (SPLIT)
                cp16(sBl + st * BK * BP + r * BP + c, Blo + g);
        }
        cp_commit();
    };

    stageLoad(0, 0);
    for (int it = 0; it < NIT; it++) {
        if (it + 1 < NIT) {
            stageLoad((it + 1) & 1, (it + 1) * BK);
            asm volatile("cp.async.wait_group 1;\n");
        } else {
            asm volatile("cp.async.wait_group 0;\n");
        }
        __syncthreads();
        int st = it & 1;
        bf16* Ab  = sAh + st * BM * AP;
        bf16* Alb = sAl + st * BM * AP;
        bf16* Bb  = sBh + st * BK * BP;
        bf16* Blb = sBl + st * BK * BP;
#pragma unroll
        for (int kk = 0; kk < BK; kk += 16) {
            wm::fragment<wm::matrix_a, 16, 16, 16, bf16, wm::row_major> ah[4];
            wm::fragment<wm::matrix_b, 16, 16, 16, bf16, wm::row_major> bhf[2];
#pragma unroll
            for (int i = 0; i < 4; i++)
                wm::load_matrix_sync(ah[i], &Ab[(wmr + i * 16) * AP + kk], AP);
#pragma unroll
            for (int j = 0; j < 2; j++)
                wm::load_matrix_sync(bhf[j], &Bb[kk * BP + wnc + j * 16], BP);
#pragma unroll
            for (int i = 0; i < 4; i++)
#pragma unroll
                for (int j = 0; j < 2; j++)
                    wm::mma_sync(acc[i][j], ah[i], bhf[j], acc[i][j]);
            if constexpr (SPLIT) {
                wm::fragment<wm::matrix_b, 16, 16, 16, bf16, wm::row_major> blf[2];
#pragma unroll
                for (int j = 0; j < 2; j++)
                    wm::load_matrix_sync(blf[j], &Blb[kk * BP + wnc + j * 16], BP);
#pragma unroll
                for (int i = 0; i < 4; i++)
#pragma unroll
                    for (int j = 0; j < 2; j++)
                        wm::mma_sync(acc[i][j], ah[i], blf[j], acc[i][j]);
                wm::fragment<wm::matrix_a, 16, 16, 16, bf16, wm::row_major> al[4];
#pragma unroll
                for (int i = 0; i < 4; i++)
                    wm::load_matrix_sync(al[i], &Alb[(wmr + i * 16) * AP + kk], AP);
#pragma unroll
                for (int i = 0; i < 4; i++)
#pragma unroll
                    for (int j = 0; j < 2; j++)
                        wm::mma_sync(acc[i][j], al[i], bhf[j], acc[i][j]);
            }
        }
        __syncthreads();
    }

    // ---- epilogue via per-warp smem staging (reuses pipeline smem) ----
    float* stg = (float*)dynsmem + warp * 264;
#pragma unroll
    for (int i = 0; i < 4; i++)
#pragma unroll
        for (int j = 0; j < 2; j++) {
            wm::store_matrix_sync(stg, acc[i][j], 16, wm::mem_row_major);
            __syncwarp();
#pragma unroll
            for (int l = 0; l < 8; l++) {
                int idx = lane + l * 32;
                int r = idx >> 4, c = idx & 15;
                int row = bm + wmr + i * 16 + r;
                int col = bn + wnc + j * 16 + c;
                float v = stg[idx];
                if constexpr (SITE == S_QKV) {
                    v += g_bqkv[col];
                    int which = col >> 9, cc = col & 511;
                    if (which < 2) v = (v > 0.f) ? (v + 1.f) : expf(v);   // elu+1
                    bf16 hi, lo; split2(v, hi, lo);
                    size_t o = (size_t)row * D + cc;
                    if (which == 0)      { g_qhi[o] = hi; g_qlo[o] = lo; }
                    else if (which == 1) { g_khi[o] = hi; g_klo[o] = lo; }
                    else                 { g_vhi[o] = hi; g_vlo[o] = lo; }
                } else if constexpr (SITE == S_ATTN) {
                    size_t o = (size_t)row * D + col;
                    g_seasonal[o] += v + bias[col];
                } else if constexpr (SITE == S_FFN1) {
                    v += bias[col];
                    v = 0.5f * v * (1.f + erff(v * 0.70710678118654752f));  // exact gelu
                    g_h[(size_t)row * DFF + col] = __float2bfloat16(v);
                } else {
                    size_t o = (size_t)row * D + col;
                    outp[o] = v + bias[col] + g_seasonal[o] + g_trend[o];
                }
            }
            __syncwarp();
        }
}

// ---------------------------------------------------------------------------
// Launch
// ---------------------------------------------------------------------------
extern "C" void kernel_launch(void* const* d_in, const int* in_sizes, int n_in,
                              void* d_out, int out_size) {
    (void)in_sizes; (void)n_in; (void)out_size;
    const float* x   = (const float*)d_in[0];
    const float* Wq  = (const float*)d_in[1];
    const float* bq  = (const float*)d_in[2];
    const float* Wk  = (const float*)d_in[3];
    const float* bk  = (const float*)d_in[4];
    const float* Wv  = (const float*)d_in[5];
    const float* bv  = (const float*)d_in[6];
    const float* Wo  = (const float*)d_in[7];
    const float* bo  = (const float*)d_in[8];
    const float* g1  = (const float*)d_in[9];
    const float* b1  = (const float*)d_in[10];
    const float* g2  = (const float*)d_in[11];
    const float* b2  = (const float*)d_in[12];
    const float* Wf1 = (const float*)d_in[13];
    const float* bf1 = (const float*)d_in[14];
    const float* Wf2 = (const float*)d_in[15];
    const float* bf2 = (const float*)d_in[16];
    float* out = (float*)d_out;

    cudaFuncSetAttribute(gemm_pipe<S_QKV>,  cudaFuncAttributeMaxDynamicSharedMemorySize,
                         GemmSmem<S_QKV>::BYTES);
    cudaFuncSetAttribute(gemm_pipe<S_ATTN>, cudaFuncAttributeMaxDynamicSharedMemorySize,
                         GemmSmem<S_ATTN>::BYTES);

    convert_weights<<<4096, 256>>>(Wq, Wk, Wv, bq, bk, bv, Wf1, Wf2);
    decomp_ln1<<<MTOK, 256>>>(x, g1, b1);
    gemm_pipe<S_QKV><<<dim3(3 * D / BN, MTOK / BM, 1), 256, GemmSmem<S_QKV>::BYTES>>>(nullptr, nullptr);
    kv_mma<<<256, 256>>>();
    kvwo_kernel<<<256, 256>>>(Wo);
    gemm_pipe<S_ATTN><<<dim3(D / BN, NSEQ / BM, B_), 256, GemmSmem<S_ATTN>::BYTES>>>(bo, nullptr);
    ln2_kernel<<<MTOK, 256>>>(g2, b2);
    gemm_pipe<S_FFN1><<<dim3(DFF / BN, MTOK / BM, 1), 256, GemmSmem<S_FFN1>::BYTES>>>(bf1, nullptr);
    gemm_pipe<S_FFN2><<<dim3(D / BN, MTOK / BM, 1), 256, GemmSmem<S_FFN2>::BYTES>>>(bf2, out);
}

// round 4
// speedup vs baseline: 1.9059x; 1.9059x over previous
#include <cuda_runtime.h>
#include <cuda_bf16.h>
#include <mma.h>
#include <math.h>
#include <stdint.h>

namespace wm = nvcuda::wmma;
using bf16 = __nv_bfloat16;

// ---------------------------------------------------------------------------
// Problem constants
// ---------------------------------------------------------------------------
constexpr int B_      = 8;
constexpr int NSEQ    = 4096;
constexpr int MTOK    = B_ * NSEQ;          // 32768
constexpr int D       = 512;
constexpr int DFF     = 2048;
constexpr int HD      = 64;                 // head dim

// ---------------------------------------------------------------------------
// Scratch (static device globals -- allocation-free contract)
// ---------------------------------------------------------------------------
__device__ __align__(16) float g_seasonal[MTOK * D];
__device__ __align__(16) float g_trend   [MTOK * D];
__device__ __align__(16) bf16  g_lnhi    [MTOK * D];
__device__ __align__(16) bf16  g_lnlo    [MTOK * D];
__device__ __align__(16) bf16  g_qhi     [MTOK * D];
__device__ __align__(16) bf16  g_qlo     [MTOK * D];
__device__ __align__(16) bf16  g_khi     [MTOK * D];
__device__ __align__(16) bf16  g_klo     [MTOK * D];
__device__ __align__(16) bf16  g_vhi     [MTOK * D];
__device__ __align__(16) bf16  g_vlo     [MTOK * D];
__device__ __align__(16) bf16  g_lnb     [MTOK * D];
__device__ __align__(16) bf16  g_h       [MTOK * DFF];
__device__ __align__(16) float g_kvp     [4 * 64 * HD * HD];
// B operands stored [N, K] K-major (transposed weights) for mma row.col
__device__ __align__(16) bf16  g_MThi    [B_ * D * D];
__device__ __align__(16) bf16  g_MTlo    [B_ * D * D];
__device__ __align__(16) bf16  g_WqkvT_hi[3 * D * D];
__device__ __align__(16) bf16  g_WqkvT_lo[3 * D * D];
__device__ __align__(16) bf16  g_Wf1T    [DFF * D];
__device__ __align__(16) bf16  g_Wf2T    [D * DFF];
__device__ __align__(16) float g_bqkv    [3 * D];

__device__ __forceinline__ void split2(float x, bf16& hi, bf16& lo) {
    hi = __float2bfloat16(x);
    lo = __float2bfloat16(x - __bfloat162float(hi));
}

__device__ __forceinline__ uint32_t smem_u32(const void* p) {
    uint32_t a;
    asm("{ .reg .u64 t; cvta.to.shared.u64 t, %1; cvt.u32.u64 %0, t; }" : "=r"(a) : "l"(p));
    return a;
}
__device__ __forceinline__ void cp16s(uint32_t saddr, const void* gptr) {
    asm volatile("cp.async.cg.shared.global [%0], [%1], 16;\n" :: "r"(saddr), "l"(gptr));
}
__device__ __forceinline__ void cp_commit() { asm volatile("cp.async.commit_group;\n"); }

__device__ __forceinline__ void ldsm4(uint32_t* r, uint32_t addr) {
    asm volatile("ldmatrix.sync.aligned.m8n8.x4.shared.b16 {%0,%1,%2,%3}, [%4];\n"
                 : "=r"(r[0]), "=r"(r[1]), "=r"(r[2]), "=r"(r[3]) : "r"(addr));
}
__device__ __forceinline__ void mma_bf16(float* d, const uint32_t* a, uint32_t b0, uint32_t b1) {
    asm volatile(
        "mma.sync.aligned.m16n8k16.row.col.f32.bf16.bf16.f32 "
        "{%0,%1,%2,%3}, {%4,%5,%6,%7}, {%8,%9}, {%0,%1,%2,%3};\n"
        : "+f"(d[0]), "+f"(d[1]), "+f"(d[2]), "+f"(d[3])
        : "r"(a[0]), "r"(a[1]), "r"(a[2]), "r"(a[3]), "r"(b0), "r"(b1));
}

// ---------------------------------------------------------------------------
// 1. Weight conversion / split / transpose (tiny, once per call)
// ---------------------------------------------------------------------------
__global__ void convert_weights(const float* __restrict__ Wq, const float* __restrict__ Wk,
                                const float* __restrict__ Wv,
                                const float* __restrict__ bq, const float* __restrict__ bk,
                                const float* __restrict__ bv,
                                const float* __restrict__ Wf1, const float* __restrict__ Wf2) {
    int i = blockIdx.x * 256 + threadIdx.x;
    if (i < D * D) {
        int r = i >> 9, c = i & 511;
        bf16 hi, lo;
        split2(Wq[i], hi, lo);
        g_WqkvT_hi[(size_t)c * D + r] = hi;  g_WqkvT_lo[(size_t)c * D + r] = lo;
        split2(Wk[i], hi, lo);
        g_WqkvT_hi[(size_t)(512 + c) * D + r] = hi;  g_WqkvT_lo[(size_t)(512 + c) * D + r] = lo;
        split2(Wv[i], hi, lo);
        g_WqkvT_hi[(size_t)(1024 + c) * D + r] = hi; g_WqkvT_lo[(size_t)(1024 + c) * D + r] = lo;
    }
    if (i < D * DFF) {
        int r = i >> 11, c = i & 2047;               // Wf1[r][c]
        g_Wf1T[(size_t)c * D + r] = __float2bfloat16(Wf1[i]);
        int r2 = i >> 9, c2 = i & 511;               // Wf2[r2][c2]
        g_Wf2T[(size_t)c2 * DFF + r2] = __float2bfloat16(Wf2[i]);
    }
    if (i < D) {
        g_bqkv[i]        = bq[i];
        g_bqkv[i + 512]  = bk[i];
        g_bqkv[i + 1024] = bv[i];
    }
}

// ---------------------------------------------------------------------------
// 2. Series decomposition + LayerNorm1 -> bf16 hi/lo
// ---------------------------------------------------------------------------
__global__ void __launch_bounds__(256) decomp_ln1(const float* __restrict__ x,
                                                  const float* __restrict__ g1,
                                                  const float* __restrict__ b1) {
    int m = blockIdx.x;
    int n = m & (NSEQ - 1);
    const float* xr = x + (size_t)m * D;
    __shared__ float sse[D];
    __shared__ float red[16];
    __shared__ float s_mean, s_inv;
    int t = threadIdx.x;
    float sum = 0.f, sq = 0.f;
#pragma unroll
    for (int i = 0; i < 2; i++) {
        int c = t + i * 256;
        float x0 = xr[c];
        float xm = (n > 0)        ? xr[c - D] : 0.f;
        float xp = (n < NSEQ - 1) ? xr[c + D] : 0.f;
        float tr = (xm + x0 + xp) * (1.f / 3.f);
        float se = x0 - tr;
        g_trend[(size_t)m * D + c]    = tr;
        g_seasonal[(size_t)m * D + c] = se;
        sse[c] = se;
        sum += se; sq += se * se;
    }
#pragma unroll
    for (int o = 16; o > 0; o >>= 1) {
        sum += __shfl_xor_sync(0xffffffffu, sum, o);
        sq  += __shfl_xor_sync(0xffffffffu, sq,  o);
    }
    if ((t & 31) == 0) { red[t >> 5] = sum; red[8 + (t >> 5)] = sq; }
    __syncthreads();
    if (t == 0) {
        float S = 0.f, Q = 0.f;
#pragma unroll
        for (int w = 0; w < 8; w++) { S += red[w]; Q += red[8 + w]; }
        float mean = S * (1.f / (float)D);
        float var  = Q * (1.f / (float)D) - mean * mean;
        s_mean = mean;
        s_inv  = rsqrtf(var + 1e-5f);
    }
    __syncthreads();
#pragma unroll
    for (int i = 0; i < 2; i++) {
        int c = t + i * 256;
        float v = (sse[c] - s_mean) * s_inv * g1[c] + b1[c];
        bf16 hi, lo; split2(v, hi, lo);
        size_t o = (size_t)m * D + c;
        g_lnhi[o] = hi;
        g_lnlo[o] = lo;
    }
}

// ---------------------------------------------------------------------------
// LayerNorm2 (seasonal -> bf16 single)
// ---------------------------------------------------------------------------
__global__ void __launch_bounds__(256) ln2_kernel(const float* __restrict__ g2,
                                                  const float* __restrict__ b2) {
    int m = blockIdx.x;
    const float* sr = g_seasonal + (size_t)m * D;
    __shared__ float sse[D];
    __shared__ float red[16];
    __shared__ float s_mean, s_inv;
    int t = threadIdx.x;
    float sum = 0.f, sq = 0.f;
#pragma unroll
    for (int i = 0; i < 2; i++) {
        int c = t + i * 256;
        float se = sr[c];
        sse[c] = se;
        sum += se; sq += se * se;
    }
#pragma unroll
    for (int o = 16; o > 0; o >>= 1) {
        sum += __shfl_xor_sync(0xffffffffu, sum, o);
        sq  += __shfl_xor_sync(0xffffffffu, sq,  o);
    }
    if ((t & 31) == 0) { red[t >> 5] = sum; red[8 + (t >> 5)] = sq; }
    __syncthreads();
    if (t == 0) {
        float S = 0.f, Q = 0.f;
#pragma unroll
        for (int w = 0; w < 8; w++) { S += red[w]; Q += red[8 + w]; }
        float mean = S * (1.f / (float)D);
        float var  = Q * (1.f / (float)D) - mean * mean;
        s_mean = mean;
        s_inv  = rsqrtf(var + 1e-5f);
    }
    __syncthreads();
#pragma unroll
    for (int i = 0; i < 2; i++) {
        int c = t + i * 256;
        float v = (sse[c] - s_mean) * s_inv * g2[c] + b2[c];
        g_lnb[(size_t)m * D + c] = __float2bfloat16(v);
    }
}

// ---------------------------------------------------------------------------
// kv partials via split-bf16 wmma (validated: ~81us)
// ---------------------------------------------------------------------------
__global__ void __launch_bounds__(256) kv_mma() {
    int bh    = blockIdx.x & 63;
    int chunk = blockIdx.x >> 6;
    int b = bh >> 3, h = bh & 7;
    size_t base = (size_t)b * NSEQ * D + h * HD;

    __shared__ __align__(16) bf16 sk [2][32][72];
    __shared__ __align__(16) bf16 skl[2][32][72];
    __shared__ __align__(16) bf16 sv [2][32][72];
    __shared__ __align__(16) bf16 svl[2][32][72];

    int t = threadIdx.x;
    int warp = t >> 5;
    int wd = (warp >> 1) * 16;
    int wf = (warp & 1) * 32;

    wm::fragment<wm::accumulator, 16, 16, 16, float> acc[2];
#pragma unroll
    for (int j = 0; j < 2; j++) wm::fill_fragment(acc[j], 0.f);

    int n0base = chunk * (NSEQ / 4);
    int r = t >> 3, c = (t & 7) * 8;

    {
        size_t g = base + (size_t)(n0base + r) * D + c;
        cp16s(smem_u32(&sk [0][r][c]), g_khi + g);
        cp16s(smem_u32(&skl[0][r][c]), g_klo + g);
        cp16s(smem_u32(&sv [0][r][c]), g_vhi + g);
        cp16s(smem_u32(&svl[0][r][c]), g_vlo + g);
        cp_commit();
    }
    constexpr int NIT = (NSEQ / 4) / 32;
    for (int it = 0; it < NIT; it++) {
        if (it + 1 < NIT) {
            int st = (it + 1) & 1;
            size_t g = base + (size_t)(n0base + (it + 1) * 32 + r) * D + c;
            cp16s(smem_u32(&sk [st][r][c]), g_khi + g);
            cp16s(smem_u32(&skl[st][r][c]), g_klo + g);
            cp16s(smem_u32(&sv [st][r][c]), g_vhi + g);
            cp16s(smem_u32(&svl[st][r][c]), g_vlo + g);
            cp_commit();
            asm volatile("cp.async.wait_group 1;\n");
        } else {
            asm volatile("cp.async.wait_group 0;\n");
        }
        __syncthreads();
        int st = it & 1;
#pragma unroll
        for (int kk = 0; kk < 32; kk += 16) {
            wm::fragment<wm::matrix_a, 16, 16, 16, bf16, wm::col_major> ah, al;
            wm::fragment<wm::matrix_b, 16, 16, 16, bf16, wm::row_major> bh[2], bl[2];
            wm::load_matrix_sync(ah, &sk [st][kk][wd], 72);
            wm::load_matrix_sync(al, &skl[st][kk][wd], 72);
#pragma unroll
            for (int j = 0; j < 2; j++) {
                wm::load_matrix_sync(bh[j], &sv [st][kk][wf + j * 16], 72);
                wm::load_matrix_sync(bl[j], &svl[st][kk][wf + j * 16], 72);
            }
#pragma unroll
            for (int j = 0; j < 2; j++) {
                wm::mma_sync(acc[j], ah, bh[j], acc[j]);
                wm::mma_sync(acc[j], ah, bl[j], acc[j]);
                wm::mma_sync(acc[j], al, bh[j], acc[j]);
            }
        }
        __syncthreads();
    }
    float* dst = g_kvp + (size_t)chunk * (64 * HD * HD) + (size_t)bh * (HD * HD);
#pragma unroll
    for (int j = 0; j < 2; j++)
        wm::store_matrix_sync(dst + wd * HD + wf + j * 16, acc[j], HD, wm::mem_row_major);
}

// ---------------------------------------------------------------------------
// M^T[b, j, h*64+d] = sum_f kv[b,h,d,f] * Wo[h*64+f, j]   (fp32, split out,
// stored transposed: the [N,K] B operand of the attn GEMM)
// ---------------------------------------------------------------------------
__global__ void __launch_bounds__(256) kvwo_kernel(const float* __restrict__ Wo) {
    int bh = blockIdx.x >> 2, jt = blockIdx.x & 3;
    int b = bh >> 3, h = bh & 7;
    __shared__ __align__(16) float skv[HD][HD];
    int t = threadIdx.x;
#pragma unroll
    for (int i = 0; i < 16; i++) {
        int idx = t + i * 256;
        float s = 0.f;
#pragma unroll
        for (int c = 0; c < 4; c++)
            s += g_kvp[(size_t)c * (64 * HD * HD) + (size_t)bh * (HD * HD) + idx];
        reinterpret_cast<float*>(skv)[idx] = s;
    }
    __syncthreads();
    int j0 = jt * 128;
    int d0 = (t >> 5) * 8;
    int jj = (t & 31) * 4;
    float acc[8][4] = {};
    for (int f = 0; f < HD; f++) {
        float4 w4 = *reinterpret_cast<const float4*>(&Wo[(size_t)(h * HD + f) * D + j0 + jj]);
        float w[4] = {w4.x, w4.y, w4.z, w4.w};
#pragma unroll
        for (int i = 0; i < 8; i++) {
            float kv = skv[d0 + i][f];
#pragma unroll
            for (int j = 0; j < 4; j++) acc[i][j] += kv * w[j];
        }
    }
#pragma unroll
    for (int i = 0; i < 8; i++)
#pragma unroll
        for (int j = 0; j < 4; j++) {
            size_t o = (size_t)b * (D * D) + (size_t)(j0 + jj + j) * D + (h * HD + d0 + i);
            bf16 hi, lo;
            split2(acc[i][j], hi, lo);
            g_MThi[o] = hi;
            g_MTlo[o] = lo;
        }
}

// ---------------------------------------------------------------------------
// Raw mma.sync GEMM engine: 128x128 CTA tile, 8 warps x (64x32), BK=32,
// 3-stage cp.async pipeline, ldmatrix operand loads, fused epilogues.
// Split sites: 3 passes (hi*hi + hi*lo + lo*hi).
// ---------------------------------------------------------------------------
#define S_QKV  0
#define S_ATTN 1
#define S_FFN1 2
#define S_FFN2 3

constexpr int NS = 3;              // pipeline stages
constexpr int AP = 40;             // smem pitch (elements)
constexpr int TILE_ELE = 128 * AP; // per array per stage
constexpr int TILE_BYTES = TILE_ELE * 2;

template <int SITE> struct McCfg {
    static constexpr bool SPLIT = (SITE == S_QKV || SITE == S_ATTN);
    static constexpr int SMEM_BYTES = (SPLIT ? 4 : 2) * NS * TILE_BYTES;
};

template <int SITE>
__global__ void __launch_bounds__(256) gemm_mma(const float* __restrict__ bias,
                                                float* __restrict__ outp) {
    constexpr bool SPLIT = McCfg<SITE>::SPLIT;
    constexpr int K   = (SITE == S_FFN2) ? 2048 : 512;
    constexpr int LDA = (SITE == S_FFN2) ? 2048 : 512;
    constexpr int LDB = (SITE == S_FFN2) ? 2048 : 512;
    constexpr int NIT = K / 32;

    extern __shared__ __align__(16) char dyn[];
    uint32_t sb = smem_u32(dyn);
    // layout: Ah[NS] | Bh[NS] | (Al[NS] | Bl[NS])
    uint32_t sAh = sb;
    uint32_t sBh = sb + NS * TILE_BYTES;
    uint32_t sAl = sb + 2 * NS * TILE_BYTES;
    uint32_t sBl = sb + 3 * NS * TILE_BYTES;

    const bf16 *Agh = nullptr, *Agl = nullptr, *Bgh = nullptr, *Bgl = nullptr;
    if constexpr (SITE == S_QKV)  { Agh = g_lnhi; Agl = g_lnlo; Bgh = g_WqkvT_hi; Bgl = g_WqkvT_lo; }
    if constexpr (SITE == S_ATTN) { Agh = g_qhi;  Agl = g_qlo;
                                    Bgh = g_MThi + (size_t)blockIdx.z * (D * D);
                                    Bgl = g_MTlo + (size_t)blockIdx.z * (D * D); }
    if constexpr (SITE == S_FFN1) { Agh = g_lnb;  Bgh = g_Wf1T; }
    if constexpr (SITE == S_FFN2) { Agh = g_h;    Bgh = g_Wf2T; }

    int bm = blockIdx.y * 128 + ((SITE == S_ATTN) ? blockIdx.z * NSEQ : 0);
    int bn = blockIdx.x * 128;
    int tid  = threadIdx.x;
    int warp = tid >> 5, lane = tid & 31;
    int wmr = (warp >> 2) * 64;   // warp m base
    int wnc = (warp & 3) * 32;    // warp n base

    float acc[4][4][4];
#pragma unroll
    for (int mi = 0; mi < 4; mi++)
#pragma unroll
        for (int ni = 0; ni < 4; ni++)
#pragma unroll
            for (int e = 0; e < 4; e++) acc[mi][ni][e] = 0.f;

    // chunk mapping: 512 x 16B chunks per 128x32 tile; 2 per thread
    int c0r = tid >> 2, c0c = (tid & 3) * 8;
    int c1r = (tid + 256) >> 2, c1c = c0c;

    auto loadStage = [&](int st, int k0) {
        uint32_t oa = (uint32_t)(st * TILE_BYTES);
        uint32_t so0 = (uint32_t)((c0r * AP + c0c) * 2);
        uint32_t so1 = (uint32_t)((c1r * AP + c1c) * 2);
        cp16s(sAh + oa + so0, Agh + (size_t)(bm + c0r) * LDA + k0 + c0c);
        cp16s(sAh + oa + so1, Agh + (size_t)(bm + c1r) * LDA + k0 + c1c);
        cp16s(sBh + oa + so0, Bgh + (size_t)(bn + c0r) * LDB + k0 + c0c);
        cp16s(sBh + oa + so1, Bgh + (size_t)(bn + c1r) * LDB + k0 + c1c);
        if constexpr (SPLIT) {
            cp16s(sAl + oa + so0, Agl + (size_t)(bm + c0r) * LDA + k0 + c0c);
            cp16s(sAl + oa + so1, Agl + (size_t)(bm + c1r) * LDA + k0 + c1c);
            cp16s(sBl + oa + so0, Bgl + (size_t)(bn + c0r) * LDB + k0 + c0c);
            cp16s(sBl + oa + so1, Bgl + (size_t)(bn + c1r) * LDB + k0 + c1c);
        }
        cp_commit();
    };

    // ldmatrix address bases (per thread)
    uint32_t lrow = (uint32_t)(lane & 15);
    uint32_t lcol = (uint32_t)(((lane >> 4) & 1) << 3);

#pragma unroll
    for (int s = 0; s < NS - 1; s++) loadStage(s, s * 32);

    for (int it = 0; it < NIT; it++) {
        if (it + NS - 1 < NIT) {
            loadStage((it + NS - 1) % NS, (it + NS - 1) * 32);
            asm volatile("cp.async.wait_group %0;\n" :: "n"(NS - 1));
        } else {
            asm volatile("cp.async.wait_group 0;\n");
        }
        __syncthreads();

        int st = it % NS;
        uint32_t oa = (uint32_t)(st * TILE_BYTES);
#pragma unroll
        for (int kk = 0; kk < 32; kk += 16) {
            uint32_t colb = (uint32_t)((kk + lcol) * 2);
            uint32_t ah[4][4], bh[2][4];
#pragma unroll
            for (int mi = 0; mi < 4; mi++)
                ldsm4(ah[mi], sAh + oa + (uint32_t)((wmr + mi * 16 + lrow) * AP * 2) + colb);
#pragma unroll
            for (int np = 0; np < 2; np++)
                ldsm4(bh[np], sBh + oa + (uint32_t)((wnc + np * 16 + lrow) * AP * 2) + colb);
#pragma unroll
            for (int mi = 0; mi < 4; mi++)
#pragma unroll
                for (int ni = 0; ni < 4; ni++)
                    mma_bf16(acc[mi][ni], ah[mi], bh[ni >> 1][ni & 1], bh[ni >> 1][(ni & 1) + 2]);
            if constexpr (SPLIT) {
                uint32_t bl[2][4];
#pragma unroll
                for (int np = 0; np < 2; np++)
                    ldsm4(bl[np], sBl + oa + (uint32_t)((wnc + np * 16 + lrow) * AP * 2) + colb);
#pragma unroll
                for (int mi = 0; mi < 4; mi++)
#pragma unroll
                    for (int ni = 0; ni < 4; ni++)
                        mma_bf16(acc[mi][ni], ah[mi], bl[ni >> 1][ni & 1], bl[ni >> 1][(ni & 1) + 2]);
                uint32_t al[4][4];
#pragma unroll
                for (int mi = 0; mi < 4; mi++)
                    ldsm4(al[mi], sAl + oa + (uint32_t)((wmr + mi * 16 + lrow) * AP * 2) + colb);
#pragma unroll
                for (int mi = 0; mi < 4; mi++)
#pragma unroll
                    for (int ni = 0; ni < 4; ni++)
                        mma_bf16(acc[mi][ni], al[mi], bh[ni >> 1][ni & 1], bh[ni >> 1][(ni & 1) + 2]);
            }
        }
        __syncthreads();
    }

    // ---- fused epilogue straight from accumulator registers ----
    int rbase = bm + wmr + (lane >> 2);
    int cbase = bn + wnc + (lane & 3) * 2;
#pragma unroll
    for (int mi = 0; mi < 4; mi++)
#pragma unroll
        for (int ni = 0; ni < 4; ni++)
#pragma unroll
            for (int hh = 0; hh < 2; hh++) {
                int row = rbase + mi * 16 + hh * 8;
                int col = cbase + ni * 8;
                float v0 = acc[mi][ni][hh * 2 + 0];
                float v1 = acc[mi][ni][hh * 2 + 1];
                if constexpr (SITE == S_QKV) {
                    v0 += g_bqkv[col];
                    v1 += g_bqkv[col + 1];
                    int which = col >> 9, cc = col & 511;
                    if (which < 2) {
                        v0 = (v0 > 0.f) ? (v0 + 1.f) : expf(v0);
                        v1 = (v1 > 0.f) ? (v1 + 1.f) : expf(v1);
                    }
                    bf16 h0, l0, h1, l1;
                    split2(v0, h0, l0); split2(v1, h1, l1);
                    uint32_t wh = (uint32_t)__bfloat16_as_ushort(h0) |
                                  ((uint32_t)__bfloat16_as_ushort(h1) << 16);
                    uint32_t wl = (uint32_t)__bfloat16_as_ushort(l0) |
                                  ((uint32_t)__bfloat16_as_ushort(l1) << 16);
                    bf16* dh = (which == 0) ? g_qhi : (which == 1) ? g_khi : g_vhi;
                    bf16* dl = (which == 0) ? g_qlo : (which == 1) ? g_klo : g_vlo;
                    size_t o = (size_t)row * D + cc;
                    *reinterpret_cast<uint32_t*>(dh + o) = wh;
                    *reinterpret_cast<uint32_t*>(dl + o) = wl;
                } else if constexpr (SITE == S_ATTN) {
                    size_t o = (size_t)row * D + col;
                    float2 s = *reinterpret_cast<float2*>(g_seasonal + o);
                    s.x += v0 + bias[col];
                    s.y += v1 + bias[col + 1];
                    *reinterpret_cast<float2*>(g_seasonal + o) = s;
                } else if constexpr (SITE == S_FFN1) {
                    v0 += bias[col];
                    v1 += bias[col + 1];
                    v0 = 0.5f * v0 * (1.f + erff(v0 * 0.70710678118654752f));
                    v1 = 0.5f * v1 * (1.f + erff(v1 * 0.70710678118654752f));
                    uint32_t wv = (uint32_t)__bfloat16_as_ushort(__float2bfloat16(v0)) |
                                  ((uint32_t)__bfloat16_as_ushort(__float2bfloat16(v1)) << 16);
                    *reinterpret_cast<uint32_t*>(g_h + (size_t)row * DFF + col) = wv;
                } else {
                    size_t o = (size_t)row * D + col;
                    float2 se = *reinterpret_cast<float2*>(g_seasonal + o);
                    float2 tr = *reinterpret_cast<float2*>(g_trend + o);
                    float2 ov;
                    ov.x = v0 + bias[col]     + se.x + tr.x;
                    ov.y = v1 + bias[col + 1] + se.y + tr.y;
                    *reinterpret_cast<float2*>(outp + o) = ov;
                }
            }
}

// ---------------------------------------------------------------------------
// Launch
// ---------------------------------------------------------------------------
extern "C" void kernel_launch(void* const* d_in, const int* in_sizes, int n_in,
                              void* d_out, int out_size) {
    (void)in_sizes; (void)n_in; (void)out_size;
    const float* x   = (const float*)d_in[0];
    const float* Wq  = (const float*)d_in[1];
    const float* bq  = (const float*)d_in[2];
    const float* Wk  = (const float*)d_in[3];
    const float* bk  = (const float*)d_in[4];
    const float* Wv  = (const float*)d_in[5];
    const float* bv  = (const float*)d_in[6];
    const float* Wo  = (const float*)d_in[7];
    const float* bo  = (const float*)d_in[8];
    const float* g1  = (const float*)d_in[9];
    const float* b1  = (const float*)d_in[10];
    const float* g2  = (const float*)d_in[11];
    const float* b2  = (const float*)d_in[12];
    const float* Wf1 = (const float*)d_in[13];
    const float* bf1 = (const float*)d_in[14];
    const float* Wf2 = (const float*)d_in[15];
    const float* bf2 = (const float*)d_in[16];
    float* out = (float*)d_out;

    cudaFuncSetAttribute(gemm_mma<S_QKV>,  cudaFuncAttributeMaxDynamicSharedMemorySize, McCfg<S_QKV>::SMEM_BYTES);
    cudaFuncSetAttribute(gemm_mma<S_ATTN>, cudaFuncAttributeMaxDynamicSharedMemorySize, McCfg<S_ATTN>::SMEM_BYTES);
    cudaFuncSetAttribute(gemm_mma<S_FFN1>, cudaFuncAttributeMaxDynamicSharedMemorySize, McCfg<S_FFN1>::SMEM_BYTES);
    cudaFuncSetAttribute(gemm_mma<S_FFN2>, cudaFuncAttributeMaxDynamicSharedMemorySize, McCfg<S_FFN2>::SMEM_BYTES);

    convert_weights<<<4096, 256>>>(Wq, Wk, Wv, bq, bk, bv, Wf1, Wf2);
    decomp_ln1<<<MTOK, 256>>>(x, g1, b1);
    gemm_mma<S_QKV><<<dim3(12, MTOK / 128, 1), 256, McCfg<S_QKV>::SMEM_BYTES>>>(nullptr, nullptr);
    kv_mma<<<256, 256>>>();
    kvwo_kernel<<<256, 256>>>(Wo);
    gemm_mma<S_ATTN><<<dim3(4, NSEQ / 128, B_), 256, McCfg<S_ATTN>::SMEM_BYTES>>>(bo, nullptr);
    ln2_kernel<<<MTOK, 256>>>(g2, b2);
    gemm_mma<S_FFN1><<<dim3(16, MTOK / 128, 1), 256, McCfg<S_FFN1>::SMEM_BYTES>>>(bf1, nullptr);
    gemm_mma<S_FFN2><<<dim3(4, MTOK / 128, 1), 256, McCfg<S_FFN2>::SMEM_BYTES>>>(bf2, out);
}

// round 8
// speedup vs baseline: 2.0648x; 1.0834x over previous
#include <cuda_runtime.h>
#include <cuda_bf16.h>
#include <mma.h>
#include <math.h>
#include <stdint.h>

namespace wm = nvcuda::wmma;
using bf16 = __nv_bfloat16;

// ---------------------------------------------------------------------------
// Problem constants
// ---------------------------------------------------------------------------
constexpr int B_      = 8;
constexpr int NSEQ    = 4096;
constexpr int MTOK    = B_ * NSEQ;          // 32768
constexpr int D       = 512;
constexpr int DFF     = 2048;
constexpr int HD      = 64;                 // head dim

// ---------------------------------------------------------------------------
// Scratch (static device globals -- allocation-free contract)
// ---------------------------------------------------------------------------
__device__ __align__(16) float g_seasonal[MTOK * D];
__device__ __align__(16) float g_trend   [MTOK * D];
__device__ __align__(16) bf16  g_lnhi    [MTOK * D];
__device__ __align__(16) bf16  g_lnlo    [MTOK * D];
__device__ __align__(16) bf16  g_qhi     [MTOK * D];
__device__ __align__(16) bf16  g_qlo     [MTOK * D];
__device__ __align__(16) bf16  g_khi     [MTOK * D];
__device__ __align__(16) bf16  g_klo     [MTOK * D];
__device__ __align__(16) bf16  g_vhi     [MTOK * D];
__device__ __align__(16) bf16  g_vlo     [MTOK * D];
__device__ __align__(16) bf16  g_lnb     [MTOK * D];
__device__ __align__(16) bf16  g_h       [MTOK * DFF];
__device__ __align__(16) float g_kvp     [4 * 64 * HD * HD];
// B operands stored [N, K] K-major (transposed weights) for mma row.col
__device__ __align__(16) bf16  g_MThi    [B_ * D * D];
__device__ __align__(16) bf16  g_MTlo    [B_ * D * D];
__device__ __align__(16) bf16  g_WqkvT_hi[3 * D * D];
__device__ __align__(16) bf16  g_WqkvT_lo[3 * D * D];
__device__ __align__(16) bf16  g_Wf1T    [DFF * D];
__device__ __align__(16) bf16  g_Wf2T    [D * DFF];
__device__ __align__(16) float g_bqkv    [3 * D];

__device__ __forceinline__ void split2(float x, bf16& hi, bf16& lo) {
    hi = __float2bfloat16(x);
    lo = __float2bfloat16(x - __bfloat162float(hi));
}

__device__ __forceinline__ uint32_t smem_u32(const void* p) {
    uint32_t a;
    asm("{ .reg .u64 t; cvta.to.shared.u64 t, %1; cvt.u32.u64 %0, t; }" : "=r"(a) : "l"(p));
    return a;
}
__device__ __forceinline__ void cp16s(uint32_t saddr, const void* gptr) {
    asm volatile("cp.async.cg.shared.global [%0], [%1], 16;\n" :: "r"(saddr), "l"(gptr));
}
__device__ __forceinline__ void cp_commit() { asm volatile("cp.async.commit_group;\n"); }

__device__ __forceinline__ void ldsm4(uint32_t* r, uint32_t addr) {
    asm volatile("ldmatrix.sync.aligned.m8n8.x4.shared.b16 {%0,%1,%2,%3}, [%4];\n"
                 : "=r"(r[0]), "=r"(r[1]), "=r"(r[2]), "=r"(r[3]) : "r"(addr));
}
__device__ __forceinline__ void mma_bf16(float* d, const uint32_t* a, uint32_t b0, uint32_t b1) {
    asm volatile(
        "mma.sync.aligned.m16n8k16.row.col.f32.bf16.bf16.f32 "
        "{%0,%1,%2,%3}, {%4,%5,%6,%7}, {%8,%9}, {%0,%1,%2,%3};\n"
        : "+f"(d[0]), "+f"(d[1]), "+f"(d[2]), "+f"(d[3])
        : "r"(a[0]), "r"(a[1]), "r"(a[2]), "r"(a[3]), "r"(b0), "r"(b1));
}

// ---------------------------------------------------------------------------
// 1. Weight conversion / split / transpose (tiny, once per call)
// ---------------------------------------------------------------------------
__global__ void convert_weights(const float* __restrict__ Wq, const float* __restrict__ Wk,
                                const float* __restrict__ Wv,
                                const float* __restrict__ bq, const float* __restrict__ bk,
                                const float* __restrict__ bv,
                                const float* __restrict__ Wf1, const float* __restrict__ Wf2) {
    int i = blockIdx.x * 256 + threadIdx.x;
    if (i < D * D) {
        int r = i >> 9, c = i & 511;
        bf16 hi, lo;
        split2(Wq[i], hi, lo);
        g_WqkvT_hi[(size_t)c * D + r] = hi;  g_WqkvT_lo[(size_t)c * D + r] = lo;
        split2(Wk[i], hi, lo);
        g_WqkvT_hi[(size_t)(512 + c) * D + r] = hi;  g_WqkvT_lo[(size_t)(512 + c) * D + r] = lo;
        split2(Wv[i], hi, lo);
        g_WqkvT_hi[(size_t)(1024 + c) * D + r] = hi; g_WqkvT_lo[(size_t)(1024 + c) * D + r] = lo;
    }
    if (i < D * DFF) {
        int r = i >> 11, c = i & 2047;               // Wf1[r][c]
        g_Wf1T[(size_t)c * D + r] = __float2bfloat16(Wf1[i]);
        int r2 = i >> 9, c2 = i & 511;               // Wf2[r2][c2]
        g_Wf2T[(size_t)c2 * DFF + r2] = __float2bfloat16(Wf2[i]);
    }
    if (i < D) {
        g_bqkv[i]        = bq[i];
        g_bqkv[i + 512]  = bk[i];
        g_bqkv[i + 1024] = bv[i];
    }
}

// ---------------------------------------------------------------------------
// 2. Series decomposition + LayerNorm1 -> bf16 hi/lo
// ---------------------------------------------------------------------------
__global__ void __launch_bounds__(256) decomp_ln1(const float* __restrict__ x,
                                                  const float* __restrict__ g1,
                                                  const float* __restrict__ b1) {
    int m = blockIdx.x;
    int n = m & (NSEQ - 1);
    const float* xr = x + (size_t)m * D;
    __shared__ float sse[D];
    __shared__ float red[16];
    __shared__ float s_mean, s_inv;
    int t = threadIdx.x;
    float sum = 0.f, sq = 0.f;
#pragma unroll
    for (int i = 0; i < 2; i++) {
        int c = t + i * 256;
        float x0 = xr[c];
        float xm = (n > 0)        ? xr[c - D] : 0.f;
        float xp = (n < NSEQ - 1) ? xr[c + D] : 0.f;
        float tr = (xm + x0 + xp) * (1.f / 3.f);
        float se = x0 - tr;
        g_trend[(size_t)m * D + c]    = tr;
        g_seasonal[(size_t)m * D + c] = se;
        sse[c] = se;
        sum += se; sq += se * se;
    }
#pragma unroll
    for (int o = 16; o > 0; o >>= 1) {
        sum += __shfl_xor_sync(0xffffffffu, sum, o);
        sq  += __shfl_xor_sync(0xffffffffu, sq,  o);
    }
    if ((t & 31) == 0) { red[t >> 5] = sum; red[8 + (t >> 5)] = sq; }
    __syncthreads();
    if (t == 0) {
        float S = 0.f, Q = 0.f;
#pragma unroll
        for (int w = 0; w < 8; w++) { S += red[w]; Q += red[8 + w]; }
        float mean = S * (1.f / (float)D);
        float var  = Q * (1.f / (float)D) - mean * mean;
        s_mean = mean;
        s_inv  = rsqrtf(var + 1e-5f);
    }
    __syncthreads();
#pragma unroll
    for (int i = 0; i < 2; i++) {
        int c = t + i * 256;
        float v = (sse[c] - s_mean) * s_inv * g1[c] + b1[c];
        bf16 hi, lo; split2(v, hi, lo);
        size_t o = (size_t)m * D + c;
        g_lnhi[o] = hi;
        g_lnlo[o] = lo;
    }
}

// ---------------------------------------------------------------------------
// LayerNorm2 (seasonal -> bf16 single)
// ---------------------------------------------------------------------------
__global__ void __launch_bounds__(256) ln2_kernel(const float* __restrict__ g2,
                                                  const float* __restrict__ b2) {
    int m = blockIdx.x;
    const float* sr = g_seasonal + (size_t)m * D;
    __shared__ float sse[D];
    __shared__ float red[16];
    __shared__ float s_mean, s_inv;
    int t = threadIdx.x;
    float sum = 0.f, sq = 0.f;
#pragma unroll
    for (int i = 0; i < 2; i++) {
        int c = t + i * 256;
        float se = sr[c];
        sse[c] = se;
        sum += se; sq += se * se;
    }
#pragma unroll
    for (int o = 16; o > 0; o >>= 1) {
        sum += __shfl_xor_sync(0xffffffffu, sum, o);
        sq  += __shfl_xor_sync(0xffffffffu, sq,  o);
    }
    if ((t & 31) == 0) { red[t >> 5] = sum; red[8 + (t >> 5)] = sq; }
    __syncthreads();
    if (t == 0) {
        float S = 0.f, Q = 0.f;
#pragma unroll
        for (int w = 0; w < 8; w++) { S += red[w]; Q += red[8 + w]; }
        float mean = S * (1.f / (float)D);
        float var  = Q * (1.f / (float)D) - mean * mean;
        s_mean = mean;
        s_inv  = rsqrtf(var + 1e-5f);
    }
    __syncthreads();
#pragma unroll
    for (int i = 0; i < 2; i++) {
        int c = t + i * 256;
        float v = (sse[c] - s_mean) * s_inv * g2[c] + b2[c];
        g_lnb[(size_t)m * D + c] = __float2bfloat16(v);
    }
}

// ---------------------------------------------------------------------------
// kv partials via split-bf16 wmma (validated: ~50us)
// ---------------------------------------------------------------------------
__global__ void __launch_bounds__(256) kv_mma() {
    int bh    = blockIdx.x & 63;
    int chunk = blockIdx.x >> 6;
    int b = bh >> 3, h = bh & 7;
    size_t base = (size_t)b * NSEQ * D + h * HD;

    __shared__ __align__(16) bf16 sk [2][32][72];
    __shared__ __align__(16) bf16 skl[2][32][72];
    __shared__ __align__(16) bf16 sv [2][32][72];
    __shared__ __align__(16) bf16 svl[2][32][72];

    int t = threadIdx.x;
    int warp = t >> 5;
    int wd = (warp >> 1) * 16;
    int wf = (warp & 1) * 32;

    wm::fragment<wm::accumulator, 16, 16, 16, float> acc[2];
#pragma unroll
    for (int j = 0; j < 2; j++) wm::fill_fragment(acc[j], 0.f);

    int n0base = chunk * (NSEQ / 4);
    int r = t >> 3, c = (t & 7) * 8;

    {
        size_t g = base + (size_t)(n0base + r) * D + c;
        cp16s(smem_u32(&sk [0][r][c]), g_khi + g);
        cp16s(smem_u32(&skl[0][r][c]), g_klo + g);
        cp16s(smem_u32(&sv [0][r][c]), g_vhi + g);
        cp16s(smem_u32(&svl[0][r][c]), g_vlo + g);
        cp_commit();
    }
    constexpr int NIT = (NSEQ / 4) / 32;
    for (int it = 0; it < NIT; it++) {
        if (it + 1 < NIT) {
            int st = (it + 1) & 1;
            size_t g = base + (size_t)(n0base + (it + 1) * 32 + r) * D + c;
            cp16s(smem_u32(&sk [st][r][c]), g_khi + g);
            cp16s(smem_u32(&skl[st][r][c]), g_klo + g);
            cp16s(smem_u32(&sv [st][r][c]), g_vhi + g);
            cp16s(smem_u32(&svl[st][r][c]), g_vlo + g);
            cp_commit();
            asm volatile("cp.async.wait_group 1;\n");
        } else {
            asm volatile("cp.async.wait_group 0;\n");
        }
        __syncthreads();
        int st = it & 1;
#pragma unroll
        for (int kk = 0; kk < 32; kk += 16) {
            wm::fragment<wm::matrix_a, 16, 16, 16, bf16, wm::col_major> ah, al;
            wm::fragment<wm::matrix_b, 16, 16, 16, bf16, wm::row_major> bh[2], bl[2];
            wm::load_matrix_sync(ah, &sk [st][kk][wd], 72);
            wm::load_matrix_sync(al, &skl[st][kk][wd], 72);
#pragma unroll
            for (int j = 0; j < 2; j++) {
                wm::load_matrix_sync(bh[j], &sv [st][kk][wf + j * 16], 72);
                wm::load_matrix_sync(bl[j], &svl[st][kk][wf + j * 16], 72);
            }
#pragma unroll
            for (int j = 0; j < 2; j++) {
                wm::mma_sync(acc[j], ah, bh[j], acc[j]);
                wm::mma_sync(acc[j], ah, bl[j], acc[j]);
                wm::mma_sync(acc[j], al, bh[j], acc[j]);
            }
        }
        __syncthreads();
    }
    float* dst = g_kvp + (size_t)chunk * (64 * HD * HD) + (size_t)bh * (HD * HD);
#pragma unroll
    for (int j = 0; j < 2; j++)
        wm::store_matrix_sync(dst + wd * HD + wf + j * 16, acc[j], HD, wm::mem_row_major);
}

// ---------------------------------------------------------------------------
// M^T[b, j, h*64+d] = sum_f kv[b,h,d,f] * Wo[h*64+f, j]   (fp32, split out,
// stored transposed: the [N,K] B operand of the attn GEMM)
// ---------------------------------------------------------------------------
__global__ void __launch_bounds__(256) kvwo_kernel(const float* __restrict__ Wo) {
    int bh = blockIdx.x >> 2, jt = blockIdx.x & 3;
    int b = bh >> 3, h = bh & 7;
    __shared__ __align__(16) float skv[HD][HD];
    int t = threadIdx.x;
#pragma unroll
    for (int i = 0; i < 16; i++) {
        int idx = t + i * 256;
        float s = 0.f;
#pragma unroll
        for (int c = 0; c < 4; c++)
            s += g_kvp[(size_t)c * (64 * HD * HD) + (size_t)bh * (HD * HD) + idx];
        reinterpret_cast<float*>(skv)[idx] = s;
    }
    __syncthreads();
    int j0 = jt * 128;
    int d0 = (t >> 5) * 8;
    int jj = (t & 31) * 4;
    float acc[8][4] = {};
    for (int f = 0; f < HD; f++) {
        float4 w4 = *reinterpret_cast<const float4*>(&Wo[(size_t)(h * HD + f) * D + j0 + jj]);
        float w[4] = {w4.x, w4.y, w4.z, w4.w};
#pragma unroll
        for (int i = 0; i < 8; i++) {
            float kv = skv[d0 + i][f];
#pragma unroll
            for (int j = 0; j < 4; j++) acc[i][j] += kv * w[j];
        }
    }
#pragma unroll
    for (int i = 0; i < 8; i++)
#pragma unroll
        for (int j = 0; j < 4; j++) {
            size_t o = (size_t)b * (D * D) + (size_t)(j0 + jj + j) * D + (h * HD + d0 + i);
            bf16 hi, lo;
            split2(acc[i][j], hi, lo);
            g_MThi[o] = hi;
            g_MTlo[o] = lo;
        }
}

// ---------------------------------------------------------------------------
// mma.sync GEMM engine v2: 128x128 CTA tile, 4 warps x (64x64 warp tile),
// BK=32, NS=2 cp.async pipeline, 2 CTAs/SM. Split sites: 3 passes.
// ---------------------------------------------------------------------------
#define S_QKV  0
#define S_ATTN 1
#define S_FFN1 2
#define S_FFN2 3

constexpr int NS = 2;
constexpr int AP = 40;                     // smem pitch (elements)
constexpr int TILE_BYTES = 128 * AP * 2;   // 10240 B per array per stage

template <int SITE> struct McCfg {
    static constexpr bool SPLIT = (SITE == S_QKV || SITE == S_ATTN);
    static constexpr int SMEM_BYTES = (SPLIT ? 4 : 2) * NS * TILE_BYTES;  // 81920 / 40960
};

template <int SITE>
__global__ void __launch_bounds__(128, 2) gemm_mma(const float* __restrict__ bias,
                                                   float* __restrict__ outp) {
    constexpr bool SPLIT = McCfg<SITE>::SPLIT;
    constexpr int K   = (SITE == S_FFN2) ? 2048 : 512;
    constexpr int LDA = (SITE == S_FFN2) ? 2048 : 512;
    constexpr int LDB = (SITE == S_FFN2) ? 2048 : 512;
    constexpr int NIT = K / 32;

    extern __shared__ __align__(16) char dyn[];
    uint32_t sb = smem_u32(dyn);
    uint32_t sAh = sb;
    uint32_t sBh = sb + NS * TILE_BYTES;
    uint32_t sAl = sb + 2 * NS * TILE_BYTES;
    uint32_t sBl = sb + 3 * NS * TILE_BYTES;

    const bf16 *Agh = nullptr, *Agl = nullptr, *Bgh = nullptr, *Bgl = nullptr;
    if constexpr (SITE == S_QKV)  { Agh = g_lnhi; Agl = g_lnlo; Bgh = g_WqkvT_hi; Bgl = g_WqkvT_lo; }
    if constexpr (SITE == S_ATTN) { Agh = g_qhi;  Agl = g_qlo;
                                    Bgh = g_MThi + (size_t)blockIdx.z * (D * D);
                                    Bgl = g_MTlo + (size_t)blockIdx.z * (D * D); }
    if constexpr (SITE == S_FFN1) { Agh = g_lnb;  Bgh = g_Wf1T; }
    if constexpr (SITE == S_FFN2) { Agh = g_h;    Bgh = g_Wf2T; }

    int bm = blockIdx.y * 128 + ((SITE == S_ATTN) ? blockIdx.z * NSEQ : 0);
    int bn = blockIdx.x * 128;
    int tid  = threadIdx.x;
    int warp = tid >> 5, lane = tid & 31;
    int wmr = (warp >> 1) * 64;   // warp m base (2x2 warp grid)
    int wnc = (warp & 1) * 64;    // warp n base

    float acc[4][8][4];
#pragma unroll
    for (int mi = 0; mi < 4; mi++)
#pragma unroll
        for (int ni = 0; ni < 8; ni++)
#pragma unroll
            for (int e = 0; e < 4; e++) acc[mi][ni][e] = 0.f;

    auto loadStage = [&](int st, int k0) {
        uint32_t oa = (uint32_t)(st * TILE_BYTES);
#pragma unroll
        for (int i = 0; i < 4; i++) {
            int idx = tid + i * 128;                   // 512 chunks = 128 rows x 4
            int r = idx >> 2, c8 = (idx & 3) * 8;
            uint32_t so = oa + (uint32_t)((r * AP + c8) * 2);
            cp16s(sAh + so, Agh + (size_t)(bm + r) * LDA + k0 + c8);
            cp16s(sBh + so, Bgh + (size_t)(bn + r) * LDB + k0 + c8);
            if constexpr (SPLIT) {
                cp16s(sAl + so, Agl + (size_t)(bm + r) * LDA + k0 + c8);
                cp16s(sBl + so, Bgl + (size_t)(bn + r) * LDB + k0 + c8);
            }
        }
        cp_commit();
    };

    uint32_t lrow = (uint32_t)(lane & 15);
    uint32_t lcol = (uint32_t)(((lane >> 4) & 1) << 3);

    loadStage(0, 0);
    for (int it = 0; it < NIT; it++) {
        if (it + 1 < NIT) {
            loadStage((it + 1) & 1, (it + 1) * 32);
            asm volatile("cp.async.wait_group 1;\n");
        } else {
            asm volatile("cp.async.wait_group 0;\n");
        }
        __syncthreads();

        int st = it & 1;
        uint32_t oa = (uint32_t)(st * TILE_BYTES);
#pragma unroll
        for (int kk = 0; kk < 32; kk += 16) {
            uint32_t colb = (uint32_t)((kk + lcol) * 2);
            uint32_t ah[4][4], bh[4][4];
#pragma unroll
            for (int mi = 0; mi < 4; mi++)
                ldsm4(ah[mi], sAh + oa + (uint32_t)((wmr + mi * 16 + lrow) * AP * 2) + colb);
#pragma unroll
            for (int nb = 0; nb < 4; nb++)
                ldsm4(bh[nb], sBh + oa + (uint32_t)((wnc + nb * 16 + lrow) * AP * 2) + colb);
#pragma unroll
            for (int mi = 0; mi < 4; mi++)
#pragma unroll
                for (int ni = 0; ni < 8; ni++)
                    mma_bf16(acc[mi][ni], ah[mi], bh[ni >> 1][ni & 1], bh[ni >> 1][(ni & 1) + 2]);
            if constexpr (SPLIT) {
                // pass 2: Al x Bh  (reuse bh, then release al)
                {
                    uint32_t al[4][4];
#pragma unroll
                    for (int mi = 0; mi < 4; mi++)
                        ldsm4(al[mi], sAl + oa + (uint32_t)((wmr + mi * 16 + lrow) * AP * 2) + colb);
#pragma unroll
                    for (int mi = 0; mi < 4; mi++)
#pragma unroll
                        for (int ni = 0; ni < 8; ni++)
                            mma_bf16(acc[mi][ni], al[mi], bh[ni >> 1][ni & 1], bh[ni >> 1][(ni & 1) + 2]);
                }
                // pass 3: Ah x Bl
                {
                    uint32_t bl[4][4];
#pragma unroll
                    for (int nb = 0; nb < 4; nb++)
                        ldsm4(bl[nb], sBl + oa + (uint32_t)((wnc + nb * 16 + lrow) * AP * 2) + colb);
#pragma unroll
                    for (int mi = 0; mi < 4; mi++)
#pragma unroll
                        for (int ni = 0; ni < 8; ni++)
                            mma_bf16(acc[mi][ni], ah[mi], bl[ni >> 1][ni & 1], bl[ni >> 1][(ni & 1) + 2]);
                }
            }
        }
        __syncthreads();
    }

    // ---- fused epilogue from accumulator registers ----
    int rbase = bm + wmr + (lane >> 2);
    int cbase = bn + wnc + (lane & 3) * 2;
#pragma unroll
    for (int mi = 0; mi < 4; mi++)
#pragma unroll
        for (int ni = 0; ni < 8; ni++)
#pragma unroll
            for (int hh = 0; hh < 2; hh++) {
                int row = rbase + mi * 16 + hh * 8;
                int col = cbase + ni * 8;
                float v0 = acc[mi][ni][hh * 2 + 0];
                float v1 = acc[mi][ni][hh * 2 + 1];
                if constexpr (SITE == S_QKV) {
                    v0 += g_bqkv[col];
                    v1 += g_bqkv[col + 1];
                    int which = col >> 9, cc = col & 511;
                    if (which < 2) {
                        v0 = (v0 > 0.f) ? (v0 + 1.f) : expf(v0);
                        v1 = (v1 > 0.f) ? (v1 + 1.f) : expf(v1);
                    }
                    bf16 h0, l0, h1, l1;
                    split2(v0, h0, l0); split2(v1, h1, l1);
                    uint32_t wh = (uint32_t)__bfloat16_as_ushort(h0) |
                                  ((uint32_t)__bfloat16_as_ushort(h1) << 16);
                    uint32_t wl = (uint32_t)__bfloat16_as_ushort(l0) |
                                  ((uint32_t)__bfloat16_as_ushort(l1) << 16);
                    bf16* dh = (which == 0) ? g_qhi : (which == 1) ? g_khi : g_vhi;
                    bf16* dl = (which == 0) ? g_qlo : (which == 1) ? g_klo : g_vlo;
                    size_t o = (size_t)row * D + cc;
                    *reinterpret_cast<uint32_t*>(dh + o) = wh;
                    *reinterpret_cast<uint32_t*>(dl + o) = wl;
                } else if constexpr (SITE == S_ATTN) {
                    size_t o = (size_t)row * D + col;
                    float2 s = *reinterpret_cast<float2*>(g_seasonal + o);
                    s.x += v0 + bias[col];
                    s.y += v1 + bias[col + 1];
                    *reinterpret_cast<float2*>(g_seasonal + o) = s;
                } else if constexpr (SITE == S_FFN1) {
                    v0 += bias[col];
                    v1 += bias[col + 1];
                    v0 = 0.5f * v0 * (1.f + erff(v0 * 0.70710678118654752f));
                    v1 = 0.5f * v1 * (1.f + erff(v1 * 0.70710678118654752f));
                    bf16 b0 = __float2bfloat16(v0), b1v = __float2bfloat16(v1);
                    uint32_t wv = (uint32_t)__bfloat16_as_ushort(b0) |
                                  ((uint32_t)__bfloat16_as_ushort(b1v) << 16);
                    *reinterpret_cast<uint32_t*>(g_h + (size_t)row * DFF + col) = wv;
                } else {
                    size_t o = (size_t)row * D + col;
                    float2 se = *reinterpret_cast<float2*>(g_seasonal + o);
                    float2 tr = *reinterpret_cast<float2*>(g_trend + o);
                    float2 ov;
                    ov.x = v0 + bias[col]     + se.x + tr.x;
                    ov.y = v1 + bias[col + 1] + se.y + tr.y;
                    *reinterpret_cast<float2*>(outp + o) = ov;
                }
            }
}

// ---------------------------------------------------------------------------
// Launch
// ---------------------------------------------------------------------------
extern "C" void kernel_launch(void* const* d_in, const int* in_sizes, int n_in,
                              void* d_out, int out_size) {
    (void)in_sizes; (void)n_in; (void)out_size;
    const float* x   = (const float*)d_in[0];
    const float* Wq  = (const float*)d_in[1];
    const float* bq  = (const float*)d_in[2];
    const float* Wk  = (const float*)d_in[3];
    const float* bk  = (const float*)d_in[4];
    const float* Wv  = (const float*)d_in[5];
    const float* bv  = (const float*)d_in[6];
    const float* Wo  = (const float*)d_in[7];
    const float* bo  = (const float*)d_in[8];
    const float* g1  = (const float*)d_in[9];
    const float* b1  = (const float*)d_in[10];
    const float* g2  = (const float*)d_in[11];
    const float* b2  = (const float*)d_in[12];
    const float* Wf1 = (const float*)d_in[13];
    const float* bf1 = (const float*)d_in[14];
    const float* Wf2 = (const float*)d_in[15];
    const float* bf2 = (const float*)d_in[16];
    float* out = (float*)d_out;

    cudaFuncSetAttribute(gemm_mma<S_QKV>,  cudaFuncAttributeMaxDynamicSharedMemorySize, McCfg<S_QKV>::SMEM_BYTES);
    cudaFuncSetAttribute(gemm_mma<S_ATTN>, cudaFuncAttributeMaxDynamicSharedMemorySize, McCfg<S_ATTN>::SMEM_BYTES);
    cudaFuncSetAttribute(gemm_mma<S_FFN1>, cudaFuncAttributeMaxDynamicSharedMemorySize, McCfg<S_FFN1>::SMEM_BYTES);
    cudaFuncSetAttribute(gemm_mma<S_FFN2>, cudaFuncAttributeMaxDynamicSharedMemorySize, McCfg<S_FFN2>::SMEM_BYTES);

    convert_weights<<<4096, 256>>>(Wq, Wk, Wv, bq, bk, bv, Wf1, Wf2);
    decomp_ln1<<<MTOK, 256>>>(x, g1, b1);
    gemm_mma<S_QKV><<<dim3(12, MTOK / 128, 1), 128, McCfg<S_QKV>::SMEM_BYTES>>>(nullptr, nullptr);
    kv_mma<<<256, 256>>>();
    kvwo_kernel<<<256, 256>>>(Wo);
    gemm_mma<S_ATTN><<<dim3(4, NSEQ / 128, B_), 128, McCfg<S_ATTN>::SMEM_BYTES>>>(bo, nullptr);
    ln2_kernel<<<MTOK, 256>>>(g2, b2);
    gemm_mma<S_FFN1><<<dim3(16, MTOK / 128, 1), 128, McCfg<S_FFN1>::SMEM_BYTES>>>(bf1, nullptr);
    gemm_mma<S_FFN2><<<dim3(4, MTOK / 128, 1), 128, McCfg<S_FFN2>::SMEM_BYTES>>>(bf2, out);
}

// round 14
// speedup vs baseline: 2.0834x; 1.0090x over previous
#include <cuda_runtime.h>
#include <cuda_bf16.h>
#include <mma.h>
#include <math.h>
#include <stdint.h>

namespace wm = nvcuda::wmma;
using bf16 = __nv_bfloat16;

// ---------------------------------------------------------------------------
// Problem constants
// ---------------------------------------------------------------------------
constexpr int B_      = 8;
constexpr int NSEQ    = 4096;
constexpr int MTOK    = B_ * NSEQ;          // 32768
constexpr int D       = 512;
constexpr int DFF     = 2048;
constexpr int HD      = 64;                 // head dim
constexpr int KVCH    = 16;                 // kv n-chunks

// ---------------------------------------------------------------------------
// Scratch (static device globals -- allocation-free contract)
// ---------------------------------------------------------------------------
__device__ __align__(16) float g_seasonal[MTOK * D];
__device__ __align__(16) float g_trend   [MTOK * D];
__device__ __align__(16) bf16  g_lnhi    [MTOK * D];
__device__ __align__(16) bf16  g_lnlo    [MTOK * D];
__device__ __align__(16) bf16  g_qhi     [MTOK * D];
__device__ __align__(16) bf16  g_qlo     [MTOK * D];
__device__ __align__(16) bf16  g_khi     [MTOK * D];
__device__ __align__(16) bf16  g_klo     [MTOK * D];
__device__ __align__(16) bf16  g_vhi     [MTOK * D];
__device__ __align__(16) bf16  g_vlo     [MTOK * D];
__device__ __align__(16) bf16  g_lnb     [MTOK * D];
__device__ __align__(16) bf16  g_h       [MTOK * DFF];
__device__ __align__(16) float g_kvp     [KVCH * 64 * HD * HD];
// B operands stored [N, K] K-major (transposed weights) for mma row.col
__device__ __align__(16) bf16  g_MThi    [B_ * D * D];
__device__ __align__(16) bf16  g_MTlo    [B_ * D * D];
__device__ __align__(16) bf16  g_WqkvT_hi[3 * D * D];
__device__ __align__(16) bf16  g_WqkvT_lo[3 * D * D];
__device__ __align__(16) bf16  g_Wf1T    [DFF * D];
__device__ __align__(16) bf16  g_Wf2T    [D * DFF];
__device__ __align__(16) float g_bqkv    [3 * D];

__device__ __forceinline__ void split2(float x, bf16& hi, bf16& lo) {
    hi = __float2bfloat16(x);
    lo = __float2bfloat16(x - __bfloat162float(hi));
}

__device__ __forceinline__ uint32_t smem_u32(const void* p) {
    uint32_t a;
    asm("{ .reg .u64 t; cvta.to.shared.u64 t, %1; cvt.u32.u64 %0, t; }" : "=r"(a) : "l"(p));
    return a;
}
__device__ __forceinline__ void cp16s(uint32_t saddr, const void* gptr) {
    asm volatile("cp.async.cg.shared.global [%0], [%1], 16;\n" :: "r"(saddr), "l"(gptr));
}
__device__ __forceinline__ void cp_commit() { asm volatile("cp.async.commit_group;\n"); }

__device__ __forceinline__ void ldsm4(uint32_t* r, uint32_t addr) {
    asm volatile("ldmatrix.sync.aligned.m8n8.x4.shared.b16 {%0,%1,%2,%3}, [%4];\n"
                 : "=r"(r[0]), "=r"(r[1]), "=r"(r[2]), "=r"(r[3]) : "r"(addr));
}
__device__ __forceinline__ void mma_bf16(float* d, const uint32_t* a, uint32_t b0, uint32_t b1) {
    asm volatile(
        "mma.sync.aligned.m16n8k16.row.col.f32.bf16.bf16.f32 "
        "{%0,%1,%2,%3}, {%4,%5,%6,%7}, {%8,%9}, {%0,%1,%2,%3};\n"
        : "+f"(d[0]), "+f"(d[1]), "+f"(d[2]), "+f"(d[3])
        : "r"(a[0]), "r"(a[1]), "r"(a[2]), "r"(a[3]), "r"(b0), "r"(b1));
}

// ---------------------------------------------------------------------------
// 1a. Weight conversion / split / transpose (tiny, once per call)
// ---------------------------------------------------------------------------
__global__ void convert_w(const float* __restrict__ Wq, const float* __restrict__ Wk,
                          const float* __restrict__ Wv,
                          const float* __restrict__ Wf1, const float* __restrict__ Wf2) {
    int i = blockIdx.x * 256 + threadIdx.x;
    if (i < D * D) {
        int r = i >> 9, c = i & 511;
        bf16 hi, lo;
        split2(Wq[i], hi, lo);
        g_WqkvT_hi[(size_t)c * D + r] = hi;  g_WqkvT_lo[(size_t)c * D + r] = lo;
        split2(Wk[i], hi, lo);
        g_WqkvT_hi[(size_t)(512 + c) * D + r] = hi;  g_WqkvT_lo[(size_t)(512 + c) * D + r] = lo;
        split2(Wv[i], hi, lo);
        g_WqkvT_hi[(size_t)(1024 + c) * D + r] = hi; g_WqkvT_lo[(size_t)(1024 + c) * D + r] = lo;
    }
    if (i < D * DFF) {
        int r = i >> 11, c = i & 2047;               // Wf1[r][c]
        g_Wf1T[(size_t)c * D + r] = __float2bfloat16(Wf1[i]);
        int r2 = i >> 9, c2 = i & 511;               // Wf2[r2][c2]
        g_Wf2T[(size_t)c2 * DFF + r2] = __float2bfloat16(Wf2[i]);
    }
}

// 1b. Bias packing (separate launch so the QKV GEMM lands in ncu's slot)
__global__ void convert_b(const float* __restrict__ bq, const float* __restrict__ bk,
                          const float* __restrict__ bv) {
    int i = blockIdx.x * 256 + threadIdx.x;
    if (i < D) {
        g_bqkv[i]        = bq[i];
        g_bqkv[i + 512]  = bk[i];
        g_bqkv[i + 1024] = bv[i];
    }
}

// ---------------------------------------------------------------------------
// 2. Series decomposition + LayerNorm1 -> bf16 hi/lo
// ---------------------------------------------------------------------------
__global__ void __launch_bounds__(256) decomp_ln1(const float* __restrict__ x,
                                                  const float* __restrict__ g1,
                                                  const float* __restrict__ b1) {
    int m = blockIdx.x;
    int n = m & (NSEQ - 1);
    const float* xr = x + (size_t)m * D;
    __shared__ float sse[D];
    __shared__ float red[16];
    __shared__ float s_mean, s_inv;
    int t = threadIdx.x;
    float sum = 0.f, sq = 0.f;
#pragma unroll
    for (int i = 0; i < 2; i++) {
        int c = t + i * 256;
        float x0 = xr[c];
        float xm = (n > 0)        ? xr[c - D] : 0.f;
        float xp = (n < NSEQ - 1) ? xr[c + D] : 0.f;
        float tr = (xm + x0 + xp) * (1.f / 3.f);
        float se = x0 - tr;
        g_trend[(size_t)m * D + c]    = tr;
        g_seasonal[(size_t)m * D + c] = se;
        sse[c] = se;
        sum += se; sq += se * se;
    }
#pragma unroll
    for (int o = 16; o > 0; o >>= 1) {
        sum += __shfl_xor_sync(0xffffffffu, sum, o);
        sq  += __shfl_xor_sync(0xffffffffu, sq,  o);
    }
    if ((t & 31) == 0) { red[t >> 5] = sum; red[8 + (t >> 5)] = sq; }
    __syncthreads();
    if (t == 0) {
        float S = 0.f, Q = 0.f;
#pragma unroll
        for (int w = 0; w < 8; w++) { S += red[w]; Q += red[8 + w]; }
        float mean = S * (1.f / (float)D);
        float var  = Q * (1.f / (float)D) - mean * mean;
        s_mean = mean;
        s_inv  = rsqrtf(var + 1e-5f);
    }
    __syncthreads();
#pragma unroll
    for (int i = 0; i < 2; i++) {
        int c = t + i * 256;
        float v = (sse[c] - s_mean) * s_inv * g1[c] + b1[c];
        bf16 hi, lo; split2(v, hi, lo);
        size_t o = (size_t)m * D + c;
        g_lnhi[o] = hi;
        g_lnlo[o] = lo;
    }
}

// ---------------------------------------------------------------------------
// LayerNorm2 (seasonal -> bf16 single)
// ---------------------------------------------------------------------------
__global__ void __launch_bounds__(256) ln2_kernel(const float* __restrict__ g2,
                                                  const float* __restrict__ b2) {
    int m = blockIdx.x;
    const float* sr = g_seasonal + (size_t)m * D;
    __shared__ float sse[D];
    __shared__ float red[16];
    __shared__ float s_mean, s_inv;
    int t = threadIdx.x;
    float sum = 0.f, sq = 0.f;
#pragma unroll
    for (int i = 0; i < 2; i++) {
        int c = t + i * 256;
        float se = sr[c];
        sse[c] = se;
        sum += se; sq += se * se;
    }
#pragma unroll
    for (int o = 16; o > 0; o >>= 1) {
        sum += __shfl_xor_sync(0xffffffffu, sum, o);
        sq  += __shfl_xor_sync(0xffffffffu, sq,  o);
    }
    if ((t & 31) == 0) { red[t >> 5] = sum; red[8 + (t >> 5)] = sq; }
    __syncthreads();
    if (t == 0) {
        float S = 0.f, Q = 0.f;
#pragma unroll
        for (int w = 0; w < 8; w++) { S += red[w]; Q += red[8 + w]; }
        float mean = S * (1.f / (float)D);
        float var  = Q * (1.f / (float)D) - mean * mean;
        s_mean = mean;
        s_inv  = rsqrtf(var + 1e-5f);
    }
    __syncthreads();
#pragma unroll
    for (int i = 0; i < 2; i++) {
        int c = t + i * 256;
        float v = (sse[c] - s_mean) * s_inv * g2[c] + b2[c];
        g_lnb[(size_t)m * D + c] = __float2bfloat16(v);
    }
}

// ---------------------------------------------------------------------------
// kv partials via split-bf16 wmma; 16 n-chunks for occupancy (grid 1024)
// ---------------------------------------------------------------------------
__global__ void __launch_bounds__(256) kv_mma() {
    int bh    = blockIdx.x & 63;
    int chunk = blockIdx.x >> 6;                    // 0..15
    int b = bh >> 3, h = bh & 7;
    size_t base = (size_t)b * NSEQ * D + h * HD;

    __shared__ __align__(16) bf16 sk [2][32][72];
    __shared__ __align__(16) bf16 skl[2][32][72];
    __shared__ __align__(16) bf16 sv [2][32][72];
    __shared__ __align__(16) bf16 svl[2][32][72];

    int t = threadIdx.x;
    int warp = t >> 5;
    int wd = (warp >> 1) * 16;
    int wf = (warp & 1) * 32;

    wm::fragment<wm::accumulator, 16, 16, 16, float> acc[2];
#pragma unroll
    for (int j = 0; j < 2; j++) wm::fill_fragment(acc[j], 0.f);

    int n0base = chunk * (NSEQ / KVCH);
    int r = t >> 3, c = (t & 7) * 8;

    {
        size_t g = base + (size_t)(n0base + r) * D + c;
        cp16s(smem_u32(&sk [0][r][c]), g_khi + g);
        cp16s(smem_u32(&skl[0][r][c]), g_klo + g);
        cp16s(smem_u32(&sv [0][r][c]), g_vhi + g);
        cp16s(smem_u32(&svl[0][r][c]), g_vlo + g);
        cp_commit();
    }
    constexpr int NIT = (NSEQ / KVCH) / 32;          // 8
    for (int it = 0; it < NIT; it++) {
        if (it + 1 < NIT) {
            int st = (it + 1) & 1;
            size_t g = base + (size_t)(n0base + (it + 1) * 32 + r) * D + c;
            cp16s(smem_u32(&sk [st][r][c]), g_khi + g);
            cp16s(smem_u32(&skl[st][r][c]), g_klo + g);
            cp16s(smem_u32(&sv [st][r][c]), g_vhi + g);
            cp16s(smem_u32(&svl[st][r][c]), g_vlo + g);
            cp_commit();
            asm volatile("cp.async.wait_group 1;\n");
        } else {
            asm volatile("cp.async.wait_group 0;\n");
        }
        __syncthreads();
        int st = it & 1;
#pragma unroll
        for (int kk = 0; kk < 32; kk += 16) {
            wm::fragment<wm::matrix_a, 16, 16, 16, bf16, wm::col_major> ah, al;
            wm::fragment<wm::matrix_b, 16, 16, 16, bf16, wm::row_major> bh[2], bl[2];
            wm::load_matrix_sync(ah, &sk [st][kk][wd], 72);
            wm::load_matrix_sync(al, &skl[st][kk][wd], 72);
#pragma unroll
            for (int j = 0; j < 2; j++) {
                wm::load_matrix_sync(bh[j], &sv [st][kk][wf + j * 16], 72);
                wm::load_matrix_sync(bl[j], &svl[st][kk][wf + j * 16], 72);
            }
#pragma unroll
            for (int j = 0; j < 2; j++) {
                wm::mma_sync(acc[j], ah, bh[j], acc[j]);
                wm::mma_sync(acc[j], ah, bl[j], acc[j]);
                wm::mma_sync(acc[j], al, bh[j], acc[j]);
            }
        }
        __syncthreads();
    }
    float* dst = g_kvp + (size_t)chunk * (64 * HD * HD) + (size_t)bh * (HD * HD);
#pragma unroll
    for (int j = 0; j < 2; j++)
        wm::store_matrix_sync(dst + wd * HD + wf + j * 16, acc[j], HD, wm::mem_row_major);
}

// ---------------------------------------------------------------------------
// M^T[b, j, h*64+d] = sum_f kv[b,h,d,f] * Wo[h*64+f, j]   (fp32, split out,
// stored transposed: the [N,K] B operand of the attn GEMM)
// ---------------------------------------------------------------------------
__global__ void __launch_bounds__(256) kvwo_kernel(const float* __restrict__ Wo) {
    int bh = blockIdx.x >> 2, jt = blockIdx.x & 3;
    int b = bh >> 3, h = bh & 7;
    __shared__ __align__(16) float skv[HD][HD];
    int t = threadIdx.x;
#pragma unroll
    for (int i = 0; i < 16; i++) {
        int idx = t + i * 256;
        float s = 0.f;
#pragma unroll
        for (int c = 0; c < KVCH; c++)
            s += g_kvp[(size_t)c * (64 * HD * HD) + (size_t)bh * (HD * HD) + idx];
        reinterpret_cast<float*>(skv)[idx] = s;
    }
    __syncthreads();
    int j0 = jt * 128;
    int d0 = (t >> 5) * 8;
    int jj = (t & 31) * 4;
    float acc[8][4] = {};
    for (int f = 0; f < HD; f++) {
        float4 w4 = *reinterpret_cast<const float4*>(&Wo[(size_t)(h * HD + f) * D + j0 + jj]);
        float w[4] = {w4.x, w4.y, w4.z, w4.w};
#pragma unroll
        for (int i = 0; i < 8; i++) {
            float kv = skv[d0 + i][f];
#pragma unroll
            for (int j = 0; j < 4; j++) acc[i][j] += kv * w[j];
        }
    }
#pragma unroll
    for (int i = 0; i < 8; i++)
#pragma unroll
        for (int j = 0; j < 4; j++) {
            size_t o = (size_t)b * (D * D) + (size_t)(j0 + jj + j) * D + (h * HD + d0 + i);
            bf16 hi, lo;
            split2(acc[i][j], hi, lo);
            g_MThi[o] = hi;
            g_MTlo[o] = lo;
        }
}

// ---------------------------------------------------------------------------
// mma.sync GEMM engine v2 (validated R8): 128x128 CTA tile, 4 warps x
// (64x64 warp tile), BK=32, NS=2 cp.async pipeline, 2 CTAs/SM.
// Split sites: 3 passes (hi*hi + lo*hi + hi*lo).
// ---------------------------------------------------------------------------
#define S_QKV  0
#define S_ATTN 1
#define S_FFN1 2
#define S_FFN2 3

constexpr int NS = 2;
constexpr int AP = 40;                     // smem pitch (elements)
constexpr int TILE_BYTES = 128 * AP * 2;   // 10240 B per array per stage

template <int SITE> struct McCfg {
    static constexpr bool SPLIT = (SITE == S_QKV || SITE == S_ATTN);
    static constexpr int SMEM_BYTES = (SPLIT ? 4 : 2) * NS * TILE_BYTES;  // 81920 / 40960
};

template <int SITE>
__global__ void __launch_bounds__(128, 2) gemm_mma(const float* __restrict__ bias,
                                                   float* __restrict__ outp) {
    constexpr bool SPLIT = McCfg<SITE>::SPLIT;
    constexpr int K   = (SITE == S_FFN2) ? 2048 : 512;
    constexpr int LDA = (SITE == S_FFN2) ? 2048 : 512;
    constexpr int LDB = (SITE == S_FFN2) ? 2048 : 512;
    constexpr int NIT = K / 32;

    extern __shared__ __align__(16) char dyn[];
    uint32_t sb = smem_u32(dyn);
    uint32_t sAh = sb;
    uint32_t sBh = sb + NS * TILE_BYTES;
    uint32_t sAl = sb + 2 * NS * TILE_BYTES;
    uint32_t sBl = sb + 3 * NS * TILE_BYTES;

    const bf16 *Agh = nullptr, *Agl = nullptr, *Bgh = nullptr, *Bgl = nullptr;
    if constexpr (SITE == S_QKV)  { Agh = g_lnhi; Agl = g_lnlo; Bgh = g_WqkvT_hi; Bgl = g_WqkvT_lo; }
    if constexpr (SITE == S_ATTN) { Agh = g_qhi;  Agl = g_qlo;
                                    Bgh = g_MThi + (size_t)blockIdx.z * (D * D);
                                    Bgl = g_MTlo + (size_t)blockIdx.z * (D * D); }
    if constexpr (SITE == S_FFN1) { Agh = g_lnb;  Bgh = g_Wf1T; }
    if constexpr (SITE == S_FFN2) { Agh = g_h;    Bgh = g_Wf2T; }

    int bm = blockIdx.y * 128 + ((SITE == S_ATTN) ? blockIdx.z * NSEQ : 0);
    int bn = blockIdx.x * 128;
    int tid  = threadIdx.x;
    int warp = tid >> 5, lane = tid & 31;
    int wmr = (warp >> 1) * 64;   // warp m base (2x2 warp grid)
    int wnc = (warp & 1) * 64;    // warp n base

    float acc[4][8][4];
#pragma unroll
    for (int mi = 0; mi < 4; mi++)
#pragma unroll
        for (int ni = 0; ni < 8; ni++)
#pragma unroll
            for (int e = 0; e < 4; e++) acc[mi][ni][e] = 0.f;

    auto loadStage = [&](int st, int k0) {
        uint32_t oa = (uint32_t)(st * TILE_BYTES);
#pragma unroll
        for (int i = 0; i < 4; i++) {
            int idx = tid + i * 128;                   // 512 chunks = 128 rows x 4
            int r = idx >> 2, c8 = (idx & 3) * 8;
            uint32_t so = oa + (uint32_t)((r * AP + c8) * 2);
            cp16s(sAh + so, Agh + (size_t)(bm + r) * LDA + k0 + c8);
            cp16s(sBh + so, Bgh + (size_t)(bn + r) * LDB + k0 + c8);
            if constexpr (SPLIT) {
                cp16s(sAl + so, Agl + (size_t)(bm + r) * LDA + k0 + c8);
                cp16s(sBl + so, Bgl + (size_t)(bn + r) * LDB + k0 + c8);
            }
        }
        cp_commit();
    };

    uint32_t lrow = (uint32_t)(lane & 15);
    uint32_t lcol = (uint32_t)(((lane >> 4) & 1) << 3);

    loadStage(0, 0);
    for (int it = 0; it < NIT; it++) {
        if (it + 1 < NIT) {
            loadStage((it + 1) & 1, (it + 1) * 32);
            asm volatile("cp.async.wait_group 1;\n");
        } else {
            asm volatile("cp.async.wait_group 0;\n");
        }
        __syncthreads();

        int st = it & 1;
        uint32_t oa = (uint32_t)(st * TILE_BYTES);
#pragma unroll
        for (int kk = 0; kk < 32; kk += 16) {
            uint32_t colb = (uint32_t)((kk + lcol) * 2);
            uint32_t ah[4][4], bh[4][4];
#pragma unroll
            for (int mi = 0; mi < 4; mi++)
                ldsm4(ah[mi], sAh + oa + (uint32_t)((wmr + mi * 16 + lrow) * AP * 2) + colb);
#pragma unroll
            for (int nb = 0; nb < 4; nb++)
                ldsm4(bh[nb], sBh + oa + (uint32_t)((wnc + nb * 16 + lrow) * AP * 2) + colb);
#pragma unroll
            for (int mi = 0; mi < 4; mi++)
#pragma unroll
                for (int ni = 0; ni < 8; ni++)
                    mma_bf16(acc[mi][ni], ah[mi], bh[ni >> 1][ni & 1], bh[ni >> 1][(ni & 1) + 2]);
            if constexpr (SPLIT) {
                // pass 2: Al x Bh  (reuse bh)
                {
                    uint32_t al[4][4];
#pragma unroll
                    for (int mi = 0; mi < 4; mi++)
                        ldsm4(al[mi], sAl + oa + (uint32_t)((wmr + mi * 16 + lrow) * AP * 2) + colb);
#pragma unroll
                    for (int mi = 0; mi < 4; mi++)
#pragma unroll
                        for (int ni = 0; ni < 8; ni++)
                            mma_bf16(acc[mi][ni], al[mi], bh[ni >> 1][ni & 1], bh[ni >> 1][(ni & 1) + 2]);
                }
                // pass 3: Ah x Bl
                {
                    uint32_t bl[4][4];
#pragma unroll
                    for (int nb = 0; nb < 4; nb++)
                        ldsm4(bl[nb], sBl + oa + (uint32_t)((wnc + nb * 16 + lrow) * AP * 2) + colb);
#pragma unroll
                    for (int mi = 0; mi < 4; mi++)
#pragma unroll
                        for (int ni = 0; ni < 8; ni++)
                            mma_bf16(acc[mi][ni], ah[mi], bl[ni >> 1][ni & 1], bl[ni >> 1][(ni & 1) + 2]);
                }
            }
        }
        __syncthreads();
    }

    // ---- fused epilogue from accumulator registers ----
    int rbase = bm + wmr + (lane >> 2);
    int cbase = bn + wnc + (lane & 3) * 2;
#pragma unroll
    for (int mi = 0; mi < 4; mi++)
#pragma unroll
        for (int ni = 0; ni < 8; ni++)
#pragma unroll
            for (int hh = 0; hh < 2; hh++) {
                int row = rbase + mi * 16 + hh * 8;
                int col = cbase + ni * 8;
                float v0 = acc[mi][ni][hh * 2 + 0];
                float v1 = acc[mi][ni][hh * 2 + 1];
                if constexpr (SITE == S_QKV) {
                    v0 += g_bqkv[col];
                    v1 += g_bqkv[col + 1];
                    int which = col >> 9, cc = col & 511;
                    if (which < 2) {
                        v0 = (v0 > 0.f) ? (v0 + 1.f) : expf(v0);
                        v1 = (v1 > 0.f) ? (v1 + 1.f) : expf(v1);
                    }
                    bf16 h0, l0, h1, l1;
                    split2(v0, h0, l0); split2(v1, h1, l1);
                    uint32_t wh = (uint32_t)__bfloat16_as_ushort(h0) |
                                  ((uint32_t)__bfloat16_as_ushort(h1) << 16);
                    uint32_t wl = (uint32_t)__bfloat16_as_ushort(l0) |
                                  ((uint32_t)__bfloat16_as_ushort(l1) << 16);
                    bf16* dh = (which == 0) ? g_qhi : (which == 1) ? g_khi : g_vhi;
                    bf16* dl = (which == 0) ? g_qlo : (which == 1) ? g_klo : g_vlo;
                    size_t o = (size_t)row * D + cc;
                    *reinterpret_cast<uint32_t*>(dh + o) = wh;
                    *reinterpret_cast<uint32_t*>(dl + o) = wl;
                } else if constexpr (SITE == S_ATTN) {
                    size_t o = (size_t)row * D + col;
                    float2 s = *reinterpret_cast<float2*>(g_seasonal + o);
                    s.x += v0 + bias[col];
                    s.y += v1 + bias[col + 1];
                    *reinterpret_cast<float2*>(g_seasonal + o) = s;
                } else if constexpr (SITE == S_FFN1) {
                    v0 += bias[col];
                    v1 += bias[col + 1];
                    v0 = 0.5f * v0 * (1.f + erff(v0 * 0.70710678118654752f));
                    v1 = 0.5f * v1 * (1.f + erff(v1 * 0.70710678118654752f));
                    bf16 b0 = __float2bfloat16(v0), b1v = __float2bfloat16(v1);
                    uint32_t wv = (uint32_t)__bfloat16_as_ushort(b0) |
                                  ((uint32_t)__bfloat16_as_ushort(b1v) << 16);
                    *reinterpret_cast<uint32_t*>(g_h + (size_t)row * DFF + col) = wv;
                } else {
                    size_t o = (size_t)row * D + col;
                    float2 se = *reinterpret_cast<float2*>(g_seasonal + o);
                    float2 tr = *reinterpret_cast<float2*>(g_trend + o);
                    float2 ov;
                    ov.x = v0 + bias[col]     + se.x + tr.x;
                    ov.y = v1 + bias[col + 1] + se.y + tr.y;
                    *reinterpret_cast<float2*>(outp + o) = ov;
                }
            }
}

// ---------------------------------------------------------------------------
// Launch (QKV GEMM deliberately the 4th launch: ncu profiles that slot)
// ---------------------------------------------------------------------------
extern "C" void kernel_launch(void* const* d_in, const int* in_sizes, int n_in,
                              void* d_out, int out_size) {
    (void)in_sizes; (void)n_in; (void)out_size;
    const float* x   = (const float*)d_in[0];
    const float* Wq  = (const float*)d_in[1];
    const float* bq  = (const float*)d_in[2];
    const float* Wk  = (const float*)d_in[3];
    const float* bk  = (const float*)d_in[4];
    const float* Wv  = (const float*)d_in[5];
    const float* bv  = (const float*)d_in[6];
    const float* Wo  = (const float*)d_in[7];
    const float* bo  = (const float*)d_in[8];
    const float* g1  = (const float*)d_in[9];
    const float* b1  = (const float*)d_in[10];
    const float* g2  = (const float*)d_in[11];
    const float* b2  = (const float*)d_in[12];
    const float* Wf1 = (const float*)d_in[13];
    const float* bf1 = (const float*)d_in[14];
    const float* Wf2 = (const float*)d_in[15];
    const float* bf2 = (const float*)d_in[16];
    float* out = (float*)d_out;

    cudaFuncSetAttribute(gemm_mma<S_QKV>,  cudaFuncAttributeMaxDynamicSharedMemorySize, McCfg<S_QKV>::SMEM_BYTES);
    cudaFuncSetAttribute(gemm_mma<S_ATTN>, cudaFuncAttributeMaxDynamicSharedMemorySize, McCfg<S_ATTN>::SMEM_BYTES);
    cudaFuncSetAttribute(gemm_mma<S_FFN1>, cudaFuncAttributeMaxDynamicSharedMemorySize, McCfg<S_FFN1>::SMEM_BYTES);
    cudaFuncSetAttribute(gemm_mma<S_FFN2>, cudaFuncAttributeMaxDynamicSharedMemorySize, McCfg<S_FFN2>::SMEM_BYTES);

    convert_w<<<4096, 256>>>(Wq, Wk, Wv, Wf1, Wf2);                                   // 1
    convert_b<<<2, 256>>>(bq, bk, bv);                                                // 2
    decomp_ln1<<<MTOK, 256>>>(x, g1, b1);                                             // 3
    gemm_mma<S_QKV><<<dim3(12, MTOK / 128, 1), 128, McCfg<S_QKV>::SMEM_BYTES>>>(nullptr, nullptr);  // 4 (profiled)
    kv_mma<<<KVCH * 64, 256>>>();                                                     // 5
    kvwo_kernel<<<256, 256>>>(Wo);                                                    // 6
    gemm_mma<S_ATTN><<<dim3(4, NSEQ / 128, B_), 128, McCfg<S_ATTN>::SMEM_BYTES>>>(bo, nullptr);
    ln2_kernel<<<MTOK, 256>>>(g2, b2);
    gemm_mma<S_FFN1><<<dim3(16, MTOK / 128, 1), 128, McCfg<S_FFN1>::SMEM_BYTES>>>(bf1, nullptr);
    gemm_mma<S_FFN2><<<dim3(4, MTOK / 128, 1), 128, McCfg<S_FFN2>::SMEM_BYTES>>>(bf2, out);
}